// round 9
// baseline (speedup 1.0000x reference)
#include <cuda_runtime.h>
#include <cuda_fp16.h>
#include <stdint.h>

#define B_   8
#define N_   2048
#define D_   64
#define H_   8
#define M_   (B_*N_)        // 16384
#define QKVN 1536
#define HD   512
#define QSCALE (0.125f * 1.44269504088896f)   // 1/sqrt(d) * log2(e)

// Scratch (__device__ globals; allocation-free rule)
__device__ __half g_q [(size_t)M_ * HD];
__device__ __half g_k [(size_t)M_ * HD];
__device__ __half g_vt[(size_t)B_*H_*D_*N_];      // [bh][d][tok]
__device__ __half g_z [(size_t)M_ * HD];
__device__ __half g_wt[64 * 520];                 // Wout^T fp16 [n][k]

// ---------------------------------------------------------------------------
// helpers
// ---------------------------------------------------------------------------
__device__ __forceinline__ float ex2f(float x) {
    float y; asm("ex2.approx.f32 %0, %1;" : "=f"(y) : "f"(x)); return y;
}
__device__ __forceinline__ uint32_t ex2h2(uint32_t x) {
    uint32_t y; asm("ex2.approx.f16x2 %0, %1;" : "=r"(y) : "r"(x)); return y;
}
__device__ __forceinline__ uint32_t packh2(float lo, float hi) {
    uint32_t u;
    asm("cvt.rn.f16x2.f32 %0, %1, %2;" : "=r"(u) : "f"(hi), "f"(lo));
    return u;
}
__device__ __forceinline__ void mma_f16(float d[4], const uint32_t a[4],
                                        uint32_t b0, uint32_t b1) {
    asm volatile(
        "mma.sync.aligned.m16n8k16.row.col.f32.f16.f16.f32 "
        "{%0,%1,%2,%3}, {%4,%5,%6,%7}, {%8,%9}, {%0,%1,%2,%3};\n"
        : "+f"(d[0]), "+f"(d[1]), "+f"(d[2]), "+f"(d[3])
        : "r"(a[0]), "r"(a[1]), "r"(a[2]), "r"(a[3]), "r"(b0), "r"(b1));
}
__device__ __forceinline__ void cp16(uint32_t dst_smem, const void* src) {
    asm volatile("cp.async.cg.shared.global [%0], [%1], 16;\n"
                 :: "r"(dst_smem), "l"(src));
}
__device__ __forceinline__ void ldsm_x4(uint32_t r[4], uint32_t addr) {
    asm volatile(
        "ldmatrix.sync.aligned.m8n8.x4.shared.b16 {%0,%1,%2,%3}, [%4];\n"
        : "=r"(r[0]), "=r"(r[1]), "=r"(r[2]), "=r"(r[3]) : "r"(addr));
}

// ---------------------------------------------------------------------------
// Wout fp32 [512][64] -> fp16 transposed [n][k] stride 520
// ---------------------------------------------------------------------------
__global__ __launch_bounds__(256)
void wconv_kernel(const float* __restrict__ W, __half* __restrict__ wt)
{
    int idx = blockIdx.x * 256 + threadIdx.x;
    int k = idx >> 6, n = idx & 63;
    wt[n * 520 + k] = __float2half_rn(W[idx]);
}

// ---------------------------------------------------------------------------
// QKV GEMM (fp16 mma): [16384,64] @ [64,1536]
// Block 64(m) x 128(n), 256 threads, warp tile 16x64.
// ---------------------------------------------------------------------------
__global__ __launch_bounds__(256)
void qkv_gemm_kernel(const float* __restrict__ x,
                     const float* __restrict__ W,
                     __half* __restrict__ q,
                     __half* __restrict__ kk,
                     __half* __restrict__ vt)
{
    __shared__ __align__(16) char smem_u[128 * 72 * 2];
    __half (*Wt)[72] = (__half(*)[72])smem_u;              // [n][k]
    __half (*sv)[72] = (__half(*)[72])smem_u;              // [col][tok] (V)

    const int tid  = threadIdx.x;
    const int warp = tid >> 5, lane = tid & 31;
    const int r = lane >> 2, qq = lane & 3;
    const int wm = warp >> 1, wn = warp & 1;
    const int n0 = blockIdx.x * 128;
    const int m0 = blockIdx.y * 64;

    #pragma unroll
    for (int it = 0; it < 8; it++) {
        int idx = tid + it * 256;
        int kw = idx >> 5;
        int c4 = idx & 31;
        float4 w = *(const float4*)(W + (size_t)kw * QKVN + n0 + c4 * 4);
        Wt[c4 * 4 + 0][kw] = __float2half_rn(w.x);
        Wt[c4 * 4 + 1][kw] = __float2half_rn(w.y);
        Wt[c4 * 4 + 2][kw] = __float2half_rn(w.z);
        Wt[c4 * 4 + 3][kw] = __float2half_rn(w.w);
    }

    uint32_t qa[4][4];
    {
        const float* p0 = x + (size_t)(m0 + wm * 16 + r) * 64;
        const float* p1 = p0 + 8 * 64;
        #pragma unroll
        for (int kt = 0; kt < 4; kt++) {
            int c = kt * 16 + 2 * qq;
            float2 a0 = *(const float2*)(p0 + c);
            float2 a1 = *(const float2*)(p1 + c);
            float2 a2 = *(const float2*)(p0 + c + 8);
            float2 a3 = *(const float2*)(p1 + c + 8);
            qa[kt][0] = packh2(a0.x, a0.y);
            qa[kt][1] = packh2(a1.x, a1.y);
            qa[kt][2] = packh2(a2.x, a2.y);
            qa[kt][3] = packh2(a3.x, a3.y);
        }
    }
    __syncthreads();

    float acc[8][4] = {};
    #pragma unroll
    for (int kt = 0; kt < 4; kt++) {
        #pragma unroll
        for (int nt = 0; nt < 8; nt++) {
            int n = wn * 64 + nt * 8 + r;
            uint32_t b0 = *(const uint32_t*)&Wt[n][kt * 16 + 2 * qq];
            uint32_t b1 = *(const uint32_t*)&Wt[n][kt * 16 + 2 * qq + 8];
            mma_f16(acc[nt], qa[kt], b0, b1);
        }
    }

    if (n0 < 1024) {
        const float s = (n0 < 512) ? QSCALE : 1.0f;
        __half* dst = (n0 < 512) ? q : kk;
        const int cbase = (n0 < 512) ? n0 : (n0 - 512);
        #pragma unroll
        for (int nt = 0; nt < 8; nt++) {
            int row0 = m0 + wm * 16 + r;
            int col  = cbase + wn * 64 + nt * 8 + 2 * qq;
            *(uint32_t*)(dst + (size_t)row0 * HD + col) =
                packh2(acc[nt][0] * s, acc[nt][1] * s);
            *(uint32_t*)(dst + (size_t)(row0 + 8) * HD + col) =
                packh2(acc[nt][2] * s, acc[nt][3] * s);
        }
    } else {
        __syncthreads();
        #pragma unroll
        for (int nt = 0; nt < 8; nt++) {
            int row_l = wm * 16 + r;
            int col_l = wn * 64 + nt * 8 + 2 * qq;
            sv[col_l    ][row_l]     = __float2half_rn(acc[nt][0]);
            sv[col_l + 1][row_l]     = __float2half_rn(acc[nt][1]);
            sv[col_l    ][row_l + 8] = __float2half_rn(acc[nt][2]);
            sv[col_l + 1][row_l + 8] = __float2half_rn(acc[nt][3]);
        }
        __syncthreads();
        const int h0   = (n0 - 1024) >> 6;
        const int b    = m0 >> 11;
        const int tok0 = m0 & 2047;
        #pragma unroll
        for (int it = 0; it < 4; it++) {
            int idx = tid + it * 256;
            int col = idx >> 3, c8 = idx & 7;
            uint4 v = *(uint4*)&sv[col][c8 * 8];
            int h = h0 + (col >> 6), d = col & 63;
            *(uint4*)(vt + ((size_t)((b * 8 + h) * 64 + d)) * N_ +
                      tok0 + c8 * 8) = v;
        }
    }
}

// ---------------------------------------------------------------------------
// Flash attention: 128 threads / 4 warps, warp = 32 q rows, LDSM fragments,
// 3-stage cp.async ring with ONE __syncthreads per KV tile.
// ---------------------------------------------------------------------------
#define VSTRIDE 88
#define KS_STAGE 8192
#define VS_STAGE (64 * VSTRIDE * 2)          // 11264
#define ATTN_SMEM (3 * (KS_STAGE + VS_STAGE))
#define NTILES (N_ / 64)

__global__ __launch_bounds__(128)
void attn_kernel(const __half* __restrict__ q,
                 const __half* __restrict__ kglb,
                 const __half* __restrict__ vt,
                 __half* __restrict__ z)
{
    extern __shared__ __align__(16) char smem_raw[];
    // layout: 3 x K stage (8192 B) then 3 x V stage (11264 B)

    const int tid  = threadIdx.x;
    const int warp = tid >> 5, lane = tid & 31;
    const int r = lane >> 2, qq = lane & 3;
    const int lrow = lane & 7;
    const int ltile = lane >> 3;
    const int bh = blockIdx.y;
    const int b = bh >> 3, h = bh & 7;
    const int q0 = blockIdx.x * 128 + warp * 32;
    const uint32_t ONE2 = 0x3C003C00u;

    uint32_t qa[2][4][4];
    #pragma unroll
    for (int mt = 0; mt < 2; mt++) {
        const __half* p0 = q + (size_t)(b * N_ + q0 + mt * 16 + r) * HD + h * D_;
        const __half* p1 = p0 + 8 * (size_t)HD;
        #pragma unroll
        for (int kt = 0; kt < 4; kt++) {
            int c = kt * 16 + 2 * qq;
            qa[mt][kt][0] = *(const uint32_t*)(p0 + c);
            qa[mt][kt][1] = *(const uint32_t*)(p1 + c);
            qa[mt][kt][2] = *(const uint32_t*)(p0 + c + 8);
            qa[mt][kt][3] = *(const uint32_t*)(p1 + c + 8);
        }
    }

    float o[2][8][4] = {};
    float lf[2][4] = {};
    float mrow[2][2] = {{-1e30f, -1e30f}, {-1e30f, -1e30f}};

    const __half* kb = kglb + (size_t)(b * N_) * HD + h * D_;
    const __half* vb = vt + (size_t)bh * D_ * N_;

    const uint32_t ks_base = (uint32_t)__cvta_generic_to_shared(smem_raw);
    const uint32_t vs_base = ks_base + 3 * KS_STAGE;

    // per-lane LDSM address components
    const uint32_t kx0 = (uint32_t)(((0 * 4 + ltile) ^ lrow) * 16) + lrow * 128;
    const uint32_t kx1 = (uint32_t)(((1 * 4 + ltile) ^ lrow) * 16) + lrow * 128;
    const uint32_t vx  = (uint32_t)((lrow * VSTRIDE + ltile * 8) * 2);

#define CP_TILE(stage, j0) do {                                               \
    _Pragma("unroll")                                                         \
    for (int it = 0; it < 4; it++) {                                          \
        int idx = tid + it * 128;                                             \
        int rr = idx >> 3, c4 = idx & 7;                                      \
        cp16(ks_base + (uint32_t)((stage) * KS_STAGE + rr * 128 +             \
                                  ((c4 ^ (rr & 7)) * 16)),                    \
             kb + (size_t)((j0) + rr) * HD + c4 * 8);                         \
    }                                                                         \
    _Pragma("unroll")                                                         \
    for (int it = 0; it < 4; it++) {                                          \
        int idx = tid + it * 128;                                             \
        int dd = idx >> 3, c8 = idx & 7;                                      \
        cp16(vs_base + (uint32_t)((stage) * VS_STAGE +                        \
                                  (dd * VSTRIDE + c8 * 8) * 2),               \
             vb + (size_t)dd * N_ + (j0) + c8 * 8);                           \
    }                                                                         \
    asm volatile("cp.async.commit_group;\n" ::);                              \
} while (0)

    CP_TILE(0, 0);
    CP_TILE(1, 64);

    int st = 0;                         // stage of tile t
    for (int t = 0; t < NTILES; t++) {
        if (t < NTILES - 1) {
            asm volatile("cp.async.wait_group 1;\n" ::);
        } else {
            asm volatile("cp.async.wait_group 0;\n" ::);
        }
        __syncthreads();                // tile t visible to all warps;
                                        // everyone done reading stage of t-1
        if (t + 2 < NTILES) {
            int st2 = st + 2; if (st2 >= 3) st2 -= 3;
            CP_TILE(st2, (t + 2) * 64); // overwrites stage read in iter t-1
        }

        const uint32_t ksb = ks_base + st * KS_STAGE;
        const uint32_t vsb = vs_base + st * VS_STAGE;

        // ---- S = Q @ K^T (LDSM.x4 + fp16 mma) ----
        float sc[2][8][4] = {};
        #pragma unroll
        for (int ktp = 0; ktp < 2; ktp++) {
            const uint32_t kx = ktp ? kx1 : kx0;
            #pragma unroll
            for (int nt = 0; nt < 8; nt++) {
                uint32_t kbf[4];
                ldsm_x4(kbf, ksb + nt * 1024 + kx);
                mma_f16(sc[0][nt], qa[0][2*ktp],   kbf[0], kbf[1]);
                mma_f16(sc[1][nt], qa[1][2*ktp],   kbf[0], kbf[1]);
                mma_f16(sc[0][nt], qa[0][2*ktp+1], kbf[2], kbf[3]);
                mma_f16(sc[1][nt], qa[1][2*ktp+1], kbf[2], kbf[3]);
            }
        }

        // ---- softmax: max -> (predicated rescale) -> P in f16x2 ----
        uint32_t pl[2][8], ph[2][8];
        #pragma unroll
        for (int mt = 0; mt < 2; mt++) {
            float mx0 = -1e30f, mx1 = -1e30f;
            #pragma unroll
            for (int nt = 0; nt < 8; nt++) {
                mx0 = fmaxf(mx0, fmaxf(sc[mt][nt][0], sc[mt][nt][1]));
                mx1 = fmaxf(mx1, fmaxf(sc[mt][nt][2], sc[mt][nt][3]));
            }
            mx0 = fmaxf(mx0, __shfl_xor_sync(0xffffffffu, mx0, 1));
            mx0 = fmaxf(mx0, __shfl_xor_sync(0xffffffffu, mx0, 2));
            mx1 = fmaxf(mx1, __shfl_xor_sync(0xffffffffu, mx1, 1));
            mx1 = fmaxf(mx1, __shfl_xor_sync(0xffffffffu, mx1, 2));
            float mn0 = fmaxf(mrow[mt][0], mx0);
            float mn1 = fmaxf(mrow[mt][1], mx1);

            if (__any_sync(0xffffffffu,
                           (mn0 > mrow[mt][0]) || (mn1 > mrow[mt][1]))) {
                float c0 = ex2f(mrow[mt][0] - mn0);
                float c1 = ex2f(mrow[mt][1] - mn1);
                #pragma unroll
                for (int nt = 0; nt < 8; nt++) {
                    o[mt][nt][0] *= c0; o[mt][nt][1] *= c0;
                    o[mt][nt][2] *= c1; o[mt][nt][3] *= c1;
                }
                lf[mt][0] *= c0; lf[mt][1] *= c0;
                lf[mt][2] *= c1; lf[mt][3] *= c1;
                mrow[mt][0] = mn0; mrow[mt][1] = mn1;
            }
            #pragma unroll
            for (int nt = 0; nt < 8; nt++) {
                pl[mt][nt] = ex2h2(packh2(sc[mt][nt][0] - mn0,
                                          sc[mt][nt][1] - mn0));
                ph[mt][nt] = ex2h2(packh2(sc[mt][nt][2] - mn1,
                                          sc[mt][nt][3] - mn1));
            }
        }

        // ---- O += P @ V ; l += P @ ones (LDSM.x4) ----
        #pragma unroll
        for (int ktp = 0; ktp < 2; ktp++) {
            uint32_t paA[2][4], paB[2][4];
            #pragma unroll
            for (int mt = 0; mt < 2; mt++) {
                paA[mt][0] = pl[mt][4*ktp + 0];
                paA[mt][1] = ph[mt][4*ktp + 0];
                paA[mt][2] = pl[mt][4*ktp + 1];
                paA[mt][3] = ph[mt][4*ktp + 1];
                paB[mt][0] = pl[mt][4*ktp + 2];
                paB[mt][1] = ph[mt][4*ktp + 2];
                paB[mt][2] = pl[mt][4*ktp + 3];
                paB[mt][3] = ph[mt][4*ktp + 3];
            }
            #pragma unroll
            for (int nt = 0; nt < 8; nt++) {
                uint32_t vbf[4];
                ldsm_x4(vbf, vsb + nt * (8 * VSTRIDE * 2) + ktp * 64 + vx);
                mma_f16(o[0][nt], paA[0], vbf[0], vbf[1]);
                mma_f16(o[1][nt], paA[1], vbf[0], vbf[1]);
                mma_f16(o[0][nt], paB[0], vbf[2], vbf[3]);
                mma_f16(o[1][nt], paB[1], vbf[2], vbf[3]);
            }
            mma_f16(lf[0], paA[0], ONE2, ONE2);
            mma_f16(lf[1], paA[1], ONE2, ONE2);
            mma_f16(lf[0], paB[0], ONE2, ONE2);
            mma_f16(lf[1], paB[1], ONE2, ONE2);
        }

        st++; if (st >= 3) st -= 3;
    }

    // ---- finalize ----
    #pragma unroll
    for (int mt = 0; mt < 2; mt++) {
        float inv0 = 1.f / lf[mt][0];
        float inv1 = 1.f / lf[mt][2];
        int row0 = q0 + mt * 16 + r;
        __half* zp0 = z + (size_t)(b * N_ + row0) * HD + h * D_;
        __half* zp1 = zp0 + 8 * (size_t)HD;
        #pragma unroll
        for (int nt = 0; nt < 8; nt++) {
            int col = nt * 8 + 2 * qq;
            *(uint32_t*)(zp0 + col) = packh2(o[mt][nt][0] * inv0,
                                             o[mt][nt][1] * inv0);
            *(uint32_t*)(zp1 + col) = packh2(o[mt][nt][2] * inv1,
                                             o[mt][nt][3] * inv1);
        }
    }
}

// ---------------------------------------------------------------------------
// Output projection (fp16 mma): [16384,512] @ [512,64] + bias -> fp32
// ---------------------------------------------------------------------------
__global__ __launch_bounds__(256)
void out_gemm_kernel(const __half* __restrict__ z,
                     const __half* __restrict__ wt,
                     const float* __restrict__ bias,
                     float* __restrict__ out)
{
    extern __shared__ char smem_raw[];
    __half*   swt = (__half*)smem_raw;                       // [64][520]
    uint32_t* as  = (uint32_t*)(smem_raw + 64 * 520 * 2);    // 2 x 128 x 32 w

    const int tid  = threadIdx.x;
    const int warp = tid >> 5, lane = tid & 31;
    const int r = lane >> 2, qq = lane & 3;
    const int m0 = blockIdx.x * 128;

    const uint32_t wt_base = (uint32_t)__cvta_generic_to_shared(swt);
    const uint32_t as_base = (uint32_t)__cvta_generic_to_shared(as);

#define CPA(stage, kc) do {                                                   \
    _Pragma("unroll")                                                         \
    for (int it = 0; it < 4; it++) {                                          \
        int idx = tid + it * 256;                                             \
        int rr = idx >> 3, c4 = idx & 7;                                      \
        cp16(as_base + (uint32_t)((stage) * 16384 + rr * 128 +                \
                                  ((c4 ^ (rr & 7)) * 16)),                    \
             z + (size_t)(m0 + rr) * HD + (kc) * 64 + c4 * 8);                \
    }                                                                         \
    asm volatile("cp.async.commit_group;\n" ::);                              \
} while (0)

    #pragma unroll
    for (int it = 0; it < 16; it++) {
        int idx = tid + it * 256;
        int n = idx >> 6, c = idx & 63;
        cp16(wt_base + (uint32_t)(n * 1040 + c * 16), wt + n * 520 + c * 8);
    }
    CPA(0, 0);

    float acc[8][4] = {};

    for (int kc = 0; kc < 8; kc++) {
        const int s = kc & 1;
        if (kc < 7) {
            CPA(s ^ 1, kc + 1);
            asm volatile("cp.async.wait_group 1;\n" ::);
        } else {
            asm volatile("cp.async.wait_group 0;\n" ::);
        }
        __syncthreads();

        const uint32_t* asw = as + s * 4096;
        const int rowa0 = warp * 16 + r;
        const int rowa1 = rowa0 + 8;

        #pragma unroll
        for (int kt = 0; kt < 4; kt++) {
            uint32_t a[4];
            a[0] = asw[rowa0 * 32 + (((2*kt)   ^ r) << 2) + qq];
            a[1] = asw[rowa1 * 32 + (((2*kt)   ^ r) << 2) + qq];
            a[2] = asw[rowa0 * 32 + (((2*kt+1) ^ r) << 2) + qq];
            a[3] = asw[rowa1 * 32 + (((2*kt+1) ^ r) << 2) + qq];
            #pragma unroll
            for (int nt = 0; nt < 8; nt++) {
                int n = nt * 8 + r;
                const __half* wp = swt + n * 520 + kc * 64 + kt * 16 + 2 * qq;
                uint32_t b0 = *(const uint32_t*)wp;
                uint32_t b1 = *(const uint32_t*)(wp + 8);
                mma_f16(acc[nt], a, b0, b1);
            }
        }
        __syncthreads();
    }

    #pragma unroll
    for (int nt = 0; nt < 8; nt++) {
        int row0 = m0 + warp * 16 + r;
        int col  = nt * 8 + 2 * qq;
        float bx = bias[col], by = bias[col + 1];
        float2 v0 = {acc[nt][0] + bx, acc[nt][1] + by};
        float2 v1 = {acc[nt][2] + bx, acc[nt][3] + by};
        *(float2*)(out + (size_t)row0 * 64 + col)       = v0;
        *(float2*)(out + (size_t)(row0 + 8) * 64 + col) = v1;
    }
}

// ---------------------------------------------------------------------------
extern "C" void kernel_launch(void* const* d_in, const int* in_sizes, int n_in,
                              void* d_out, int out_size)
{
    const float* x    = (const float*)d_in[0];
    const float* Wqkv = (const float*)d_in[1];
    const float* Wout = (const float*)d_in[2];
    const float* bout = (const float*)d_in[3];
    float* out = (float*)d_out;

    __half *qp, *kp, *vtp, *zp, *wtp;
    cudaGetSymbolAddress((void**)&qp,  g_q);
    cudaGetSymbolAddress((void**)&kp,  g_k);
    cudaGetSymbolAddress((void**)&vtp, g_vt);
    cudaGetSymbolAddress((void**)&zp,  g_z);
    cudaGetSymbolAddress((void**)&wtp, g_wt);

    wconv_kernel<<<128, 256>>>(Wout, wtp);
    {
        dim3 grid(QKVN / 128, M_ / 64);
        qkv_gemm_kernel<<<grid, 256>>>(x, Wqkv, qp, kp, vtp);
    }
    {
        cudaFuncSetAttribute(attn_kernel,
                             cudaFuncAttributeMaxDynamicSharedMemorySize,
                             ATTN_SMEM);
        dim3 grid(N_ / 128, B_ * H_);
        attn_kernel<<<grid, 128, ATTN_SMEM>>>(qp, kp, vtp, zp);
    }
    {
        const int smem = 64 * 520 * 2 + 2 * 16384;   // 99328 B
        cudaFuncSetAttribute(out_gemm_kernel,
                             cudaFuncAttributeMaxDynamicSharedMemorySize, smem);
        out_gemm_kernel<<<M_ / 128, 256, smem>>>(zp, wtp, bout, out);
    }
}

// round 10
// speedup vs baseline: 1.5484x; 1.5484x over previous
#include <cuda_runtime.h>
#include <cuda_fp16.h>
#include <stdint.h>

#define B_   8
#define N_   2048
#define D_   64
#define H_   8
#define M_   (B_*N_)        // 16384
#define QKVN 1536
#define HD   512
#define QSCALE (0.125f * 1.44269504088896f)   // 1/sqrt(d) * log2(e)

// Scratch (__device__ globals; allocation-free rule)
__device__ __half g_q [(size_t)M_ * HD];
__device__ __half g_k [(size_t)M_ * HD];
__device__ __half g_vt[(size_t)B_*H_*D_*N_];      // [bh][d][tok]
__device__ __half g_z [(size_t)M_ * HD];
__device__ __half g_wt[64 * 520];                 // Wout^T fp16 [n][k]

// ---------------------------------------------------------------------------
// helpers
// ---------------------------------------------------------------------------
__device__ __forceinline__ float ex2f(float x) {
    float y; asm("ex2.approx.f32 %0, %1;" : "=f"(y) : "f"(x)); return y;
}
__device__ __forceinline__ uint32_t ex2h2(uint32_t x) {
    uint32_t y; asm("ex2.approx.f16x2 %0, %1;" : "=r"(y) : "r"(x)); return y;
}
__device__ __forceinline__ uint32_t packh2(float lo, float hi) {
    uint32_t u;
    asm("cvt.rn.f16x2.f32 %0, %1, %2;" : "=r"(u) : "f"(hi), "f"(lo));
    return u;
}
__device__ __forceinline__ void mma_f16(float d[4], const uint32_t a[4],
                                        uint32_t b0, uint32_t b1) {
    asm volatile(
        "mma.sync.aligned.m16n8k16.row.col.f32.f16.f16.f32 "
        "{%0,%1,%2,%3}, {%4,%5,%6,%7}, {%8,%9}, {%0,%1,%2,%3};\n"
        : "+f"(d[0]), "+f"(d[1]), "+f"(d[2]), "+f"(d[3])
        : "r"(a[0]), "r"(a[1]), "r"(a[2]), "r"(a[3]), "r"(b0), "r"(b1));
}
__device__ __forceinline__ void cp16(uint32_t dst_smem, const void* src) {
    asm volatile("cp.async.cg.shared.global [%0], [%1], 16;\n"
                 :: "r"(dst_smem), "l"(src));
}
__device__ __forceinline__ void ldsm_x4(uint32_t r[4], uint32_t addr) {
    asm volatile(
        "ldmatrix.sync.aligned.m8n8.x4.shared.b16 {%0,%1,%2,%3}, [%4];\n"
        : "=r"(r[0]), "=r"(r[1]), "=r"(r[2]), "=r"(r[3]) : "r"(addr));
}

// ---------------------------------------------------------------------------
// Wout fp32 [512][64] -> fp16 transposed [n][k] stride 520
// ---------------------------------------------------------------------------
__global__ __launch_bounds__(256)
void wconv_kernel(const float* __restrict__ W, __half* __restrict__ wt)
{
    int idx = blockIdx.x * 256 + threadIdx.x;
    int k = idx >> 6, n = idx & 63;
    wt[n * 520 + k] = __float2half_rn(W[idx]);
}

// ---------------------------------------------------------------------------
// QKV GEMM (fp16 mma): [16384,64] @ [64,1536]
// Block 64(m) x 128(n), 256 threads, warp tile 16x64.
// ---------------------------------------------------------------------------
__global__ __launch_bounds__(256)
void qkv_gemm_kernel(const float* __restrict__ x,
                     const float* __restrict__ W,
                     __half* __restrict__ q,
                     __half* __restrict__ kk,
                     __half* __restrict__ vt)
{
    __shared__ __align__(16) char smem_u[128 * 72 * 2];
    __half (*Wt)[72] = (__half(*)[72])smem_u;              // [n][k]
    __half (*sv)[72] = (__half(*)[72])smem_u;              // [col][tok] (V)

    const int tid  = threadIdx.x;
    const int warp = tid >> 5, lane = tid & 31;
    const int r = lane >> 2, qq = lane & 3;
    const int wm = warp >> 1, wn = warp & 1;
    const int n0 = blockIdx.x * 128;
    const int m0 = blockIdx.y * 64;

    #pragma unroll
    for (int it = 0; it < 8; it++) {
        int idx = tid + it * 256;
        int kw = idx >> 5;
        int c4 = idx & 31;
        float4 w = *(const float4*)(W + (size_t)kw * QKVN + n0 + c4 * 4);
        Wt[c4 * 4 + 0][kw] = __float2half_rn(w.x);
        Wt[c4 * 4 + 1][kw] = __float2half_rn(w.y);
        Wt[c4 * 4 + 2][kw] = __float2half_rn(w.z);
        Wt[c4 * 4 + 3][kw] = __float2half_rn(w.w);
    }

    uint32_t qa[4][4];
    {
        const float* p0 = x + (size_t)(m0 + wm * 16 + r) * 64;
        const float* p1 = p0 + 8 * 64;
        #pragma unroll
        for (int kt = 0; kt < 4; kt++) {
            int c = kt * 16 + 2 * qq;
            float2 a0 = *(const float2*)(p0 + c);
            float2 a1 = *(const float2*)(p1 + c);
            float2 a2 = *(const float2*)(p0 + c + 8);
            float2 a3 = *(const float2*)(p1 + c + 8);
            qa[kt][0] = packh2(a0.x, a0.y);
            qa[kt][1] = packh2(a1.x, a1.y);
            qa[kt][2] = packh2(a2.x, a2.y);
            qa[kt][3] = packh2(a3.x, a3.y);
        }
    }
    __syncthreads();

    float acc[8][4] = {};
    #pragma unroll
    for (int kt = 0; kt < 4; kt++) {
        #pragma unroll
        for (int nt = 0; nt < 8; nt++) {
            int n = wn * 64 + nt * 8 + r;
            uint32_t b0 = *(const uint32_t*)&Wt[n][kt * 16 + 2 * qq];
            uint32_t b1 = *(const uint32_t*)&Wt[n][kt * 16 + 2 * qq + 8];
            mma_f16(acc[nt], qa[kt], b0, b1);
        }
    }

    if (n0 < 1024) {
        const float s = (n0 < 512) ? QSCALE : 1.0f;
        __half* dst = (n0 < 512) ? q : kk;
        const int cbase = (n0 < 512) ? n0 : (n0 - 512);
        #pragma unroll
        for (int nt = 0; nt < 8; nt++) {
            int row0 = m0 + wm * 16 + r;
            int col  = cbase + wn * 64 + nt * 8 + 2 * qq;
            *(uint32_t*)(dst + (size_t)row0 * HD + col) =
                packh2(acc[nt][0] * s, acc[nt][1] * s);
            *(uint32_t*)(dst + (size_t)(row0 + 8) * HD + col) =
                packh2(acc[nt][2] * s, acc[nt][3] * s);
        }
    } else {
        __syncthreads();
        #pragma unroll
        for (int nt = 0; nt < 8; nt++) {
            int row_l = wm * 16 + r;
            int col_l = wn * 64 + nt * 8 + 2 * qq;
            sv[col_l    ][row_l]     = __float2half_rn(acc[nt][0]);
            sv[col_l + 1][row_l]     = __float2half_rn(acc[nt][1]);
            sv[col_l    ][row_l + 8] = __float2half_rn(acc[nt][2]);
            sv[col_l + 1][row_l + 8] = __float2half_rn(acc[nt][3]);
        }
        __syncthreads();
        const int h0   = (n0 - 1024) >> 6;
        const int b    = m0 >> 11;
        const int tok0 = m0 & 2047;
        #pragma unroll
        for (int it = 0; it < 4; it++) {
            int idx = tid + it * 256;
            int col = idx >> 3, c8 = idx & 7;
            uint4 v = *(uint4*)&sv[col][c8 * 8];
            int h = h0 + (col >> 6), d = col & 63;
            *(uint4*)(vt + ((size_t)((b * 8 + h) * 64 + d)) * N_ +
                      tok0 + c8 * 8) = v;
        }
    }
}

// ---------------------------------------------------------------------------
// Flash attention: 128 threads / 4 warps, warp = 32 q rows, LDSM fragments,
// 3-stage cp.async ring with ONE __syncthreads per KV tile.
// ---------------------------------------------------------------------------
#define VSTRIDE 88
#define KS_STAGE 8192
#define VS_STAGE (64 * VSTRIDE * 2)          // 11264
#define ATTN_SMEM (3 * (KS_STAGE + VS_STAGE))
#define NTILES (N_ / 64)

__global__ __launch_bounds__(128)
void attn_kernel(const __half* __restrict__ q,
                 const __half* __restrict__ kglb,
                 const __half* __restrict__ vt,
                 __half* __restrict__ z)
{
    extern __shared__ __align__(16) char smem_raw[];
    // layout: 3 x K stage (8192 B) then 3 x V stage (11264 B)

    const int tid  = threadIdx.x;
    const int warp = tid >> 5, lane = tid & 31;
    const int r = lane >> 2, qq = lane & 3;
    const int lrow = lane & 7;
    const int ltile = lane >> 3;
    const int bh = blockIdx.y;
    const int b = bh >> 3, h = bh & 7;
    const int q0 = blockIdx.x * 128 + warp * 32;
    const uint32_t ONE2 = 0x3C003C00u;

    uint32_t qa[2][4][4];
    #pragma unroll
    for (int mt = 0; mt < 2; mt++) {
        const __half* p0 = q + (size_t)(b * N_ + q0 + mt * 16 + r) * HD + h * D_;
        const __half* p1 = p0 + 8 * (size_t)HD;
        #pragma unroll
        for (int kt = 0; kt < 4; kt++) {
            int c = kt * 16 + 2 * qq;
            qa[mt][kt][0] = *(const uint32_t*)(p0 + c);
            qa[mt][kt][1] = *(const uint32_t*)(p1 + c);
            qa[mt][kt][2] = *(const uint32_t*)(p0 + c + 8);
            qa[mt][kt][3] = *(const uint32_t*)(p1 + c + 8);
        }
    }

    float o[2][8][4] = {};
    float lf[2][4] = {};
    float mrow[2][2] = {{-1e30f, -1e30f}, {-1e30f, -1e30f}};

    const __half* kb = kglb + (size_t)(b * N_) * HD + h * D_;
    const __half* vb = vt + (size_t)bh * D_ * N_;

    const uint32_t ks_base = (uint32_t)__cvta_generic_to_shared(smem_raw);
    const uint32_t vs_base = ks_base + 3 * KS_STAGE;

    // per-lane LDSM address components
    const uint32_t kx0 = (uint32_t)(((0 * 4 + ltile) ^ lrow) * 16) + lrow * 128;
    const uint32_t kx1 = (uint32_t)(((1 * 4 + ltile) ^ lrow) * 16) + lrow * 128;
    const uint32_t vx  = (uint32_t)((lrow * VSTRIDE + ltile * 8) * 2);

#define CP_TILE(stage, j0) do {                                               \
    _Pragma("unroll")                                                         \
    for (int it = 0; it < 4; it++) {                                          \
        int idx = tid + it * 128;                                             \
        int rr = idx >> 3, c4 = idx & 7;                                      \
        cp16(ks_base + (uint32_t)((stage) * KS_STAGE + rr * 128 +             \
                                  ((c4 ^ (rr & 7)) * 16)),                    \
             kb + (size_t)((j0) + rr) * HD + c4 * 8);                         \
    }                                                                         \
    _Pragma("unroll")                                                         \
    for (int it = 0; it < 4; it++) {                                          \
        int idx = tid + it * 128;                                             \
        int dd = idx >> 3, c8 = idx & 7;                                      \
        cp16(vs_base + (uint32_t)((stage) * VS_STAGE +                        \
                                  (dd * VSTRIDE + c8 * 8) * 2),               \
             vb + (size_t)dd * N_ + (j0) + c8 * 8);                           \
    }                                                                         \
    asm volatile("cp.async.commit_group;\n" ::);                              \
} while (0)

    CP_TILE(0, 0);
    CP_TILE(1, 64);

    int st = 0;                         // stage of tile t
    for (int t = 0; t < NTILES; t++) {
        if (t < NTILES - 1) {
            asm volatile("cp.async.wait_group 1;\n" ::);
        } else {
            asm volatile("cp.async.wait_group 0;\n" ::);
        }
        __syncthreads();                // tile t visible to all warps;
                                        // everyone done reading stage of t-1
        if (t + 2 < NTILES) {
            int st2 = st + 2; if (st2 >= 3) st2 -= 3;
            CP_TILE(st2, (t + 2) * 64); // overwrites stage read in iter t-1
        }

        const uint32_t ksb = ks_base + st * KS_STAGE;
        const uint32_t vsb = vs_base + st * VS_STAGE;

        // ---- S = Q @ K^T (LDSM.x4 + fp16 mma) ----
        float sc[2][8][4] = {};
        #pragma unroll
        for (int ktp = 0; ktp < 2; ktp++) {
            const uint32_t kx = ktp ? kx1 : kx0;
            #pragma unroll
            for (int nt = 0; nt < 8; nt++) {
                uint32_t kbf[4];
                ldsm_x4(kbf, ksb + nt * 1024 + kx);
                mma_f16(sc[0][nt], qa[0][2*ktp],   kbf[0], kbf[1]);
                mma_f16(sc[1][nt], qa[1][2*ktp],   kbf[0], kbf[1]);
                mma_f16(sc[0][nt], qa[0][2*ktp+1], kbf[2], kbf[3]);
                mma_f16(sc[1][nt], qa[1][2*ktp+1], kbf[2], kbf[3]);
            }
        }

        // ---- softmax: max -> (predicated rescale) -> P in f16x2 ----
        uint32_t pl[2][8], ph[2][8];
        #pragma unroll
        for (int mt = 0; mt < 2; mt++) {
            float mx0 = -1e30f, mx1 = -1e30f;
            #pragma unroll
            for (int nt = 0; nt < 8; nt++) {
                mx0 = fmaxf(mx0, fmaxf(sc[mt][nt][0], sc[mt][nt][1]));
                mx1 = fmaxf(mx1, fmaxf(sc[mt][nt][2], sc[mt][nt][3]));
            }
            mx0 = fmaxf(mx0, __shfl_xor_sync(0xffffffffu, mx0, 1));
            mx0 = fmaxf(mx0, __shfl_xor_sync(0xffffffffu, mx0, 2));
            mx1 = fmaxf(mx1, __shfl_xor_sync(0xffffffffu, mx1, 1));
            mx1 = fmaxf(mx1, __shfl_xor_sync(0xffffffffu, mx1, 2));
            float mn0 = fmaxf(mrow[mt][0], mx0);
            float mn1 = fmaxf(mrow[mt][1], mx1);

            if (__any_sync(0xffffffffu,
                           (mn0 > mrow[mt][0]) || (mn1 > mrow[mt][1]))) {
                float c0 = ex2f(mrow[mt][0] - mn0);
                float c1 = ex2f(mrow[mt][1] - mn1);
                #pragma unroll
                for (int nt = 0; nt < 8; nt++) {
                    o[mt][nt][0] *= c0; o[mt][nt][1] *= c0;
                    o[mt][nt][2] *= c1; o[mt][nt][3] *= c1;
                }
                lf[mt][0] *= c0; lf[mt][1] *= c0;
                lf[mt][2] *= c1; lf[mt][3] *= c1;
                mrow[mt][0] = mn0; mrow[mt][1] = mn1;
            }
            #pragma unroll
            for (int nt = 0; nt < 8; nt++) {
                pl[mt][nt] = ex2h2(packh2(sc[mt][nt][0] - mn0,
                                          sc[mt][nt][1] - mn0));
                ph[mt][nt] = ex2h2(packh2(sc[mt][nt][2] - mn1,
                                          sc[mt][nt][3] - mn1));
            }
        }

        // ---- O += P @ V ; l += P @ ones (LDSM.x4) ----
        #pragma unroll
        for (int ktp = 0; ktp < 2; ktp++) {
            uint32_t paA[2][4], paB[2][4];
            #pragma unroll
            for (int mt = 0; mt < 2; mt++) {
                paA[mt][0] = pl[mt][4*ktp + 0];
                paA[mt][1] = ph[mt][4*ktp + 0];
                paA[mt][2] = pl[mt][4*ktp + 1];
                paA[mt][3] = ph[mt][4*ktp + 1];
                paB[mt][0] = pl[mt][4*ktp + 2];
                paB[mt][1] = ph[mt][4*ktp + 2];
                paB[mt][2] = pl[mt][4*ktp + 3];
                paB[mt][3] = ph[mt][4*ktp + 3];
            }
            #pragma unroll
            for (int nt = 0; nt < 8; nt++) {
                uint32_t vbf[4];
                ldsm_x4(vbf, vsb + nt * (8 * VSTRIDE * 2) + ktp * 64 + vx);
                mma_f16(o[0][nt], paA[0], vbf[0], vbf[1]);
                mma_f16(o[1][nt], paA[1], vbf[0], vbf[1]);
                mma_f16(o[0][nt], paB[0], vbf[2], vbf[3]);
                mma_f16(o[1][nt], paB[1], vbf[2], vbf[3]);
            }
            mma_f16(lf[0], paA[0], ONE2, ONE2);
            mma_f16(lf[1], paA[1], ONE2, ONE2);
            mma_f16(lf[0], paB[0], ONE2, ONE2);
            mma_f16(lf[1], paB[1], ONE2, ONE2);
        }

        st++; if (st >= 3) st -= 3;
    }

    // ---- finalize ----
    #pragma unroll
    for (int mt = 0; mt < 2; mt++) {
        float inv0 = 1.f / lf[mt][0];
        float inv1 = 1.f / lf[mt][2];
        int row0 = q0 + mt * 16 + r;
        __half* zp0 = z + (size_t)(b * N_ + row0) * HD + h * D_;
        __half* zp1 = zp0 + 8 * (size_t)HD;
        #pragma unroll
        for (int nt = 0; nt < 8; nt++) {
            int col = nt * 8 + 2 * qq;
            *(uint32_t*)(zp0 + col) = packh2(o[mt][nt][0] * inv0,
                                             o[mt][nt][1] * inv0);
            *(uint32_t*)(zp1 + col) = packh2(o[mt][nt][2] * inv1,
                                             o[mt][nt][3] * inv1);
        }
    }
}

// ---------------------------------------------------------------------------
// Output projection (fp16 mma): [16384,512] @ [512,64] + bias -> fp32
// ---------------------------------------------------------------------------
__global__ __launch_bounds__(256)
void out_gemm_kernel(const __half* __restrict__ z,
                     const __half* __restrict__ wt,
                     const float* __restrict__ bias,
                     float* __restrict__ out)
{
    extern __shared__ char smem_raw[];
    __half*   swt = (__half*)smem_raw;                       // [64][520]
    uint32_t* as  = (uint32_t*)(smem_raw + 64 * 520 * 2);    // 2 x 128 x 32 w

    const int tid  = threadIdx.x;
    const int warp = tid >> 5, lane = tid & 31;
    const int r = lane >> 2, qq = lane & 3;
    const int m0 = blockIdx.x * 128;

    const uint32_t wt_base = (uint32_t)__cvta_generic_to_shared(swt);
    const uint32_t as_base = (uint32_t)__cvta_generic_to_shared(as);

#define CPA(stage, kc) do {                                                   \
    _Pragma("unroll")                                                         \
    for (int it = 0; it < 4; it++) {                                          \
        int idx = tid + it * 256;                                             \
        int rr = idx >> 3, c4 = idx & 7;                                      \
        cp16(as_base + (uint32_t)((stage) * 16384 + rr * 128 +                \
                                  ((c4 ^ (rr & 7)) * 16)),                    \
             z + (size_t)(m0 + rr) * HD + (kc) * 64 + c4 * 8);                \
    }                                                                         \
    asm volatile("cp.async.commit_group;\n" ::);                              \
} while (0)

    #pragma unroll
    for (int it = 0; it < 16; it++) {
        int idx = tid + it * 256;
        int n = idx >> 6, c = idx & 63;
        cp16(wt_base + (uint32_t)(n * 1040 + c * 16), wt + n * 520 + c * 8);
    }
    CPA(0, 0);

    float acc[8][4] = {};

    for (int kc = 0; kc < 8; kc++) {
        const int s = kc & 1;
        if (kc < 7) {
            CPA(s ^ 1, kc + 1);
            asm volatile("cp.async.wait_group 1;\n" ::);
        } else {
            asm volatile("cp.async.wait_group 0;\n" ::);
        }
        __syncthreads();

        const uint32_t* asw = as + s * 4096;
        const int rowa0 = warp * 16 + r;
        const int rowa1 = rowa0 + 8;

        #pragma unroll
        for (int kt = 0; kt < 4; kt++) {
            uint32_t a[4];
            a[0] = asw[rowa0 * 32 + (((2*kt)   ^ r) << 2) + qq];
            a[1] = asw[rowa1 * 32 + (((2*kt)   ^ r) << 2) + qq];
            a[2] = asw[rowa0 * 32 + (((2*kt+1) ^ r) << 2) + qq];
            a[3] = asw[rowa1 * 32 + (((2*kt+1) ^ r) << 2) + qq];
            #pragma unroll
            for (int nt = 0; nt < 8; nt++) {
                int n = nt * 8 + r;
                const __half* wp = swt + n * 520 + kc * 64 + kt * 16 + 2 * qq;
                uint32_t b0 = *(const uint32_t*)wp;
                uint32_t b1 = *(const uint32_t*)(wp + 8);
                mma_f16(acc[nt], a, b0, b1);
            }
        }
        __syncthreads();
    }

    #pragma unroll
    for (int nt = 0; nt < 8; nt++) {
        int row0 = m0 + warp * 16 + r;
        int col  = nt * 8 + 2 * qq;
        float bx = bias[col], by = bias[col + 1];
        float2 v0 = {acc[nt][0] + bx, acc[nt][1] + by};
        float2 v1 = {acc[nt][2] + bx, acc[nt][3] + by};
        *(float2*)(out + (size_t)row0 * 64 + col)       = v0;
        *(float2*)(out + (size_t)(row0 + 8) * 64 + col) = v1;
    }
}

// ---------------------------------------------------------------------------
extern "C" void kernel_launch(void* const* d_in, const int* in_sizes, int n_in,
                              void* d_out, int out_size)
{
    const float* x    = (const float*)d_in[0];
    const float* Wqkv = (const float*)d_in[1];
    const float* Wout = (const float*)d_in[2];
    const float* bout = (const float*)d_in[3];
    float* out = (float*)d_out;

    __half *qp, *kp, *vtp, *zp, *wtp;
    cudaGetSymbolAddress((void**)&qp,  g_q);
    cudaGetSymbolAddress((void**)&kp,  g_k);
    cudaGetSymbolAddress((void**)&vtp, g_vt);
    cudaGetSymbolAddress((void**)&zp,  g_z);
    cudaGetSymbolAddress((void**)&wtp, g_wt);

    wconv_kernel<<<128, 256>>>(Wout, wtp);
    {
        dim3 grid(QKVN / 128, M_ / 64);
        qkv_gemm_kernel<<<grid, 256>>>(x, Wqkv, qp, kp, vtp);
    }
    {
        cudaFuncSetAttribute(attn_kernel,
                             cudaFuncAttributeMaxDynamicSharedMemorySize,
                             ATTN_SMEM);
        dim3 grid(N_ / 128, B_ * H_);
        attn_kernel<<<grid, 128, ATTN_SMEM>>>(qp, kp, vtp, zp);
    }
    {
        const int smem = 64 * 520 * 2 + 2 * 16384;   // 99328 B
        cudaFuncSetAttribute(out_gemm_kernel,
                             cudaFuncAttributeMaxDynamicSharedMemorySize, smem);
        out_gemm_kernel<<<M_ / 128, 256, smem>>>(zp, wtp, bout, out);
    }
}

// round 11
// speedup vs baseline: 1.6679x; 1.0771x over previous
#include <cuda_runtime.h>
#include <cuda_fp16.h>
#include <stdint.h>

#define B_   8
#define N_   2048
#define D_   64
#define H_   8
#define M_   (B_*N_)        // 16384
#define QKVN 1536
#define HD   512
#define QSCALE (0.125f * 1.44269504088896f)   // 1/sqrt(d) * log2(e)

// Scratch (__device__ globals; allocation-free rule)
__device__ __half g_q [(size_t)M_ * HD];
__device__ __half g_k [(size_t)M_ * HD];
__device__ __half g_vt[(size_t)B_*H_*D_*N_];      // [bh][d][tok]
__device__ __half g_z [(size_t)M_ * HD];
__device__ __half g_wt[64 * 520];                 // Wout^T fp16 [n][k]

// ---------------------------------------------------------------------------
// helpers
// ---------------------------------------------------------------------------
__device__ __forceinline__ uint32_t ex2h2(uint32_t x) {
    uint32_t y; asm("ex2.approx.f16x2 %0, %1;" : "=r"(y) : "r"(x)); return y;
}
__device__ __forceinline__ uint32_t packh2(float lo, float hi) {
    uint32_t u;
    asm("cvt.rn.f16x2.f32 %0, %1, %2;" : "=r"(u) : "f"(hi), "f"(lo));
    return u;
}
__device__ __forceinline__ void mma_f16(float d[4], const uint32_t a[4],
                                        uint32_t b0, uint32_t b1) {
    asm volatile(
        "mma.sync.aligned.m16n8k16.row.col.f32.f16.f16.f32 "
        "{%0,%1,%2,%3}, {%4,%5,%6,%7}, {%8,%9}, {%0,%1,%2,%3};\n"
        : "+f"(d[0]), "+f"(d[1]), "+f"(d[2]), "+f"(d[3])
        : "r"(a[0]), "r"(a[1]), "r"(a[2]), "r"(a[3]), "r"(b0), "r"(b1));
}
__device__ __forceinline__ void cp16(uint32_t dst_smem, const void* src) {
    asm volatile("cp.async.cg.shared.global [%0], [%1], 16;\n"
                 :: "r"(dst_smem), "l"(src));
}
__device__ __forceinline__ void ldsm_x4(uint32_t r[4], uint32_t addr) {
    asm volatile(
        "ldmatrix.sync.aligned.m8n8.x4.shared.b16 {%0,%1,%2,%3}, [%4];\n"
        : "=r"(r[0]), "=r"(r[1]), "=r"(r[2]), "=r"(r[3]) : "r"(addr));
}

// ---------------------------------------------------------------------------
// Wout fp32 [512][64] -> fp16 transposed [n][k] stride 520
// ---------------------------------------------------------------------------
__global__ __launch_bounds__(256)
void wconv_kernel(const float* __restrict__ W, __half* __restrict__ wt)
{
    int idx = blockIdx.x * 256 + threadIdx.x;
    int k = idx >> 6, n = idx & 63;
    wt[n * 520 + k] = __float2half_rn(W[idx]);
}

// ---------------------------------------------------------------------------
// QKV GEMM (fp16 mma): [16384,64] @ [64,1536]
// Block 64(m) x 128(n), 256 threads, warp tile 16x64.
// ---------------------------------------------------------------------------
__global__ __launch_bounds__(256)
void qkv_gemm_kernel(const float* __restrict__ x,
                     const float* __restrict__ W,
                     __half* __restrict__ q,
                     __half* __restrict__ kk,
                     __half* __restrict__ vt)
{
    __shared__ __align__(16) char smem_u[128 * 72 * 2];
    __half (*Wt)[72] = (__half(*)[72])smem_u;              // [n][k]
    __half (*sv)[72] = (__half(*)[72])smem_u;              // [col][tok] (V)

    const int tid  = threadIdx.x;
    const int warp = tid >> 5, lane = tid & 31;
    const int r = lane >> 2, qq = lane & 3;
    const int wm = warp >> 1, wn = warp & 1;
    const int n0 = blockIdx.x * 128;
    const int m0 = blockIdx.y * 64;

    #pragma unroll
    for (int it = 0; it < 8; it++) {
        int idx = tid + it * 256;
        int kw = idx >> 5;
        int c4 = idx & 31;
        float4 w = *(const float4*)(W + (size_t)kw * QKVN + n0 + c4 * 4);
        Wt[c4 * 4 + 0][kw] = __float2half_rn(w.x);
        Wt[c4 * 4 + 1][kw] = __float2half_rn(w.y);
        Wt[c4 * 4 + 2][kw] = __float2half_rn(w.z);
        Wt[c4 * 4 + 3][kw] = __float2half_rn(w.w);
    }

    uint32_t qa[4][4];
    {
        const float* p0 = x + (size_t)(m0 + wm * 16 + r) * 64;
        const float* p1 = p0 + 8 * 64;
        #pragma unroll
        for (int kt = 0; kt < 4; kt++) {
            int c = kt * 16 + 2 * qq;
            float2 a0 = *(const float2*)(p0 + c);
            float2 a1 = *(const float2*)(p1 + c);
            float2 a2 = *(const float2*)(p0 + c + 8);
            float2 a3 = *(const float2*)(p1 + c + 8);
            qa[kt][0] = packh2(a0.x, a0.y);
            qa[kt][1] = packh2(a1.x, a1.y);
            qa[kt][2] = packh2(a2.x, a2.y);
            qa[kt][3] = packh2(a3.x, a3.y);
        }
    }
    __syncthreads();

    float acc[8][4] = {};
    #pragma unroll
    for (int kt = 0; kt < 4; kt++) {
        #pragma unroll
        for (int nt = 0; nt < 8; nt++) {
            int n = wn * 64 + nt * 8 + r;
            uint32_t b0 = *(const uint32_t*)&Wt[n][kt * 16 + 2 * qq];
            uint32_t b1 = *(const uint32_t*)&Wt[n][kt * 16 + 2 * qq + 8];
            mma_f16(acc[nt], qa[kt], b0, b1);
        }
    }

    if (n0 < 1024) {
        const float s = (n0 < 512) ? QSCALE : 1.0f;
        __half* dst = (n0 < 512) ? q : kk;
        const int cbase = (n0 < 512) ? n0 : (n0 - 512);
        #pragma unroll
        for (int nt = 0; nt < 8; nt++) {
            int row0 = m0 + wm * 16 + r;
            int col  = cbase + wn * 64 + nt * 8 + 2 * qq;
            *(uint32_t*)(dst + (size_t)row0 * HD + col) =
                packh2(acc[nt][0] * s, acc[nt][1] * s);
            *(uint32_t*)(dst + (size_t)(row0 + 8) * HD + col) =
                packh2(acc[nt][2] * s, acc[nt][3] * s);
        }
    } else {
        __syncthreads();
        #pragma unroll
        for (int nt = 0; nt < 8; nt++) {
            int row_l = wm * 16 + r;
            int col_l = wn * 64 + nt * 8 + 2 * qq;
            sv[col_l    ][row_l]     = __float2half_rn(acc[nt][0]);
            sv[col_l + 1][row_l]     = __float2half_rn(acc[nt][1]);
            sv[col_l    ][row_l + 8] = __float2half_rn(acc[nt][2]);
            sv[col_l + 1][row_l + 8] = __float2half_rn(acc[nt][3]);
        }
        __syncthreads();
        const int h0   = (n0 - 1024) >> 6;
        const int b    = m0 >> 11;
        const int tok0 = m0 & 2047;
        #pragma unroll
        for (int it = 0; it < 4; it++) {
            int idx = tid + it * 256;
            int col = idx >> 3, c8 = idx & 7;
            uint4 v = *(uint4*)&sv[col][c8 * 8];
            int h = h0 + (col >> 6), d = col & 63;
            *(uint4*)(vt + ((size_t)((b * 8 + h) * 64 + d)) * N_ +
                      tok0 + c8 * 8) = v;
        }
    }
}

// ---------------------------------------------------------------------------
// Flash attention: 128 threads / 4 warps, warp = 32 q rows, LDSM fragments,
// 3-stage cp.async ring, FROZEN per-row softmax offset (tile-0 max; no
// online rescale, no per-tile reductions).
// ---------------------------------------------------------------------------
#define VSTRIDE 88
#define KS_STAGE 8192
#define VS_STAGE (64 * VSTRIDE * 2)          // 11264
#define ATTN_SMEM (3 * (KS_STAGE + VS_STAGE))
#define NTILES (N_ / 64)

__global__ __launch_bounds__(128)
void attn_kernel(const __half* __restrict__ q,
                 const __half* __restrict__ kglb,
                 const __half* __restrict__ vt,
                 __half* __restrict__ z)
{
    extern __shared__ __align__(16) char smem_raw[];
    // layout: 3 x K stage (8192 B) then 3 x V stage (11264 B)

    const int tid  = threadIdx.x;
    const int warp = tid >> 5, lane = tid & 31;
    const int r = lane >> 2, qq = lane & 3;
    const int lrow = lane & 7;
    const int ltile = lane >> 3;
    const int bh = blockIdx.y;
    const int b = bh >> 3, h = bh & 7;
    const int q0 = blockIdx.x * 128 + warp * 32;
    const uint32_t ONE2 = 0x3C003C00u;

    uint32_t qa[2][4][4];
    #pragma unroll
    for (int mt = 0; mt < 2; mt++) {
        const __half* p0 = q + (size_t)(b * N_ + q0 + mt * 16 + r) * HD + h * D_;
        const __half* p1 = p0 + 8 * (size_t)HD;
        #pragma unroll
        for (int kt = 0; kt < 4; kt++) {
            int c = kt * 16 + 2 * qq;
            qa[mt][kt][0] = *(const uint32_t*)(p0 + c);
            qa[mt][kt][1] = *(const uint32_t*)(p1 + c);
            qa[mt][kt][2] = *(const uint32_t*)(p0 + c + 8);
            qa[mt][kt][3] = *(const uint32_t*)(p1 + c + 8);
        }
    }

    float o[2][8][4] = {};
    float lf[2][4] = {};
    float mrow[2][2];                     // frozen after tile 0

    const __half* kb = kglb + (size_t)(b * N_) * HD + h * D_;
    const __half* vb = vt + (size_t)bh * D_ * N_;

    const uint32_t ks_base = (uint32_t)__cvta_generic_to_shared(smem_raw);
    const uint32_t vs_base = ks_base + 3 * KS_STAGE;

    // per-lane LDSM address components
    const uint32_t kx0 = (uint32_t)(((0 * 4 + ltile) ^ lrow) * 16) + lrow * 128;
    const uint32_t kx1 = (uint32_t)(((1 * 4 + ltile) ^ lrow) * 16) + lrow * 128;
    const uint32_t vx  = (uint32_t)((lrow * VSTRIDE + ltile * 8) * 2);

#define CP_TILE(stage, j0) do {                                               \
    _Pragma("unroll")                                                         \
    for (int it = 0; it < 4; it++) {                                          \
        int idx = tid + it * 128;                                             \
        int rr = idx >> 3, c4 = idx & 7;                                      \
        cp16(ks_base + (uint32_t)((stage) * KS_STAGE + rr * 128 +             \
                                  ((c4 ^ (rr & 7)) * 16)),                    \
             kb + (size_t)((j0) + rr) * HD + c4 * 8);                         \
    }                                                                         \
    _Pragma("unroll")                                                         \
    for (int it = 0; it < 4; it++) {                                          \
        int idx = tid + it * 128;                                             \
        int dd = idx >> 3, c8 = idx & 7;                                      \
        cp16(vs_base + (uint32_t)((stage) * VS_STAGE +                        \
                                  (dd * VSTRIDE + c8 * 8) * 2),               \
             vb + (size_t)dd * N_ + (j0) + c8 * 8);                           \
    }                                                                         \
    asm volatile("cp.async.commit_group;\n" ::);                              \
} while (0)

    CP_TILE(0, 0);
    CP_TILE(1, 64);

    int st = 0;                         // stage of tile t
    for (int t = 0; t < NTILES; t++) {
        if (t < NTILES - 1) {
            asm volatile("cp.async.wait_group 1;\n" ::);
        } else {
            asm volatile("cp.async.wait_group 0;\n" ::);
        }
        __syncthreads();                // tile t visible to all warps;
                                        // everyone done reading stage of t-1
        if (t + 2 < NTILES) {
            int st2 = st + 2; if (st2 >= 3) st2 -= 3;
            CP_TILE(st2, (t + 2) * 64); // overwrites stage read in iter t-1
        }

        const uint32_t ksb = ks_base + st * KS_STAGE;
        const uint32_t vsb = vs_base + st * VS_STAGE;

        // ---- S = Q @ K^T (LDSM.x4 + fp16 mma) ----
        float sc[2][8][4] = {};
        #pragma unroll
        for (int ktp = 0; ktp < 2; ktp++) {
            const uint32_t kx = ktp ? kx1 : kx0;
            #pragma unroll
            for (int nt = 0; nt < 8; nt++) {
                uint32_t kbf[4];
                ldsm_x4(kbf, ksb + nt * 1024 + kx);
                mma_f16(sc[0][nt], qa[0][2*ktp],   kbf[0], kbf[1]);
                mma_f16(sc[1][nt], qa[1][2*ktp],   kbf[0], kbf[1]);
                mma_f16(sc[0][nt], qa[0][2*ktp+1], kbf[2], kbf[3]);
                mma_f16(sc[1][nt], qa[1][2*ktp+1], kbf[2], kbf[3]);
            }
        }

        // ---- tile 0 only: compute the frozen per-row offset ----
        if (t == 0) {
            #pragma unroll
            for (int mt = 0; mt < 2; mt++) {
                float mx0 = -1e30f, mx1 = -1e30f;
                #pragma unroll
                for (int nt = 0; nt < 8; nt++) {
                    mx0 = fmaxf(mx0, fmaxf(sc[mt][nt][0], sc[mt][nt][1]));
                    mx1 = fmaxf(mx1, fmaxf(sc[mt][nt][2], sc[mt][nt][3]));
                }
                mx0 = fmaxf(mx0, __shfl_xor_sync(0xffffffffu, mx0, 1));
                mx0 = fmaxf(mx0, __shfl_xor_sync(0xffffffffu, mx0, 2));
                mx1 = fmaxf(mx1, __shfl_xor_sync(0xffffffffu, mx1, 1));
                mx1 = fmaxf(mx1, __shfl_xor_sync(0xffffffffu, mx1, 2));
                mrow[mt][0] = mx0;
                mrow[mt][1] = mx1;
            }
        }

        // ---- P = exp2(S - m_frozen) in f16x2 (no reductions, no rescale) ----
        uint32_t pl[2][8], ph[2][8];
        #pragma unroll
        for (int mt = 0; mt < 2; mt++) {
            const float mn0 = mrow[mt][0];
            const float mn1 = mrow[mt][1];
            #pragma unroll
            for (int nt = 0; nt < 8; nt++) {
                pl[mt][nt] = ex2h2(packh2(sc[mt][nt][0] - mn0,
                                          sc[mt][nt][1] - mn0));
                ph[mt][nt] = ex2h2(packh2(sc[mt][nt][2] - mn1,
                                          sc[mt][nt][3] - mn1));
            }
        }

        // ---- O += P @ V ; l += P @ ones (LDSM.x4) ----
        #pragma unroll
        for (int ktp = 0; ktp < 2; ktp++) {
            uint32_t paA[2][4], paB[2][4];
            #pragma unroll
            for (int mt = 0; mt < 2; mt++) {
                paA[mt][0] = pl[mt][4*ktp + 0];
                paA[mt][1] = ph[mt][4*ktp + 0];
                paA[mt][2] = pl[mt][4*ktp + 1];
                paA[mt][3] = ph[mt][4*ktp + 1];
                paB[mt][0] = pl[mt][4*ktp + 2];
                paB[mt][1] = ph[mt][4*ktp + 2];
                paB[mt][2] = pl[mt][4*ktp + 3];
                paB[mt][3] = ph[mt][4*ktp + 3];
            }
            #pragma unroll
            for (int nt = 0; nt < 8; nt++) {
                uint32_t vbf[4];
                ldsm_x4(vbf, vsb + nt * (8 * VSTRIDE * 2) + ktp * 64 + vx);
                mma_f16(o[0][nt], paA[0], vbf[0], vbf[1]);
                mma_f16(o[1][nt], paA[1], vbf[0], vbf[1]);
                mma_f16(o[0][nt], paB[0], vbf[2], vbf[3]);
                mma_f16(o[1][nt], paB[1], vbf[2], vbf[3]);
            }
            mma_f16(lf[0], paA[0], ONE2, ONE2);
            mma_f16(lf[1], paA[1], ONE2, ONE2);
            mma_f16(lf[0], paB[0], ONE2, ONE2);
            mma_f16(lf[1], paB[1], ONE2, ONE2);
        }

        st++; if (st >= 3) st -= 3;
    }

    // ---- finalize ----
    #pragma unroll
    for (int mt = 0; mt < 2; mt++) {
        float inv0 = 1.f / lf[mt][0];
        float inv1 = 1.f / lf[mt][2];
        int row0 = q0 + mt * 16 + r;
        __half* zp0 = z + (size_t)(b * N_ + row0) * HD + h * D_;
        __half* zp1 = zp0 + 8 * (size_t)HD;
        #pragma unroll
        for (int nt = 0; nt < 8; nt++) {
            int col = nt * 8 + 2 * qq;
            *(uint32_t*)(zp0 + col) = packh2(o[mt][nt][0] * inv0,
                                             o[mt][nt][1] * inv0);
            *(uint32_t*)(zp1 + col) = packh2(o[mt][nt][2] * inv1,
                                             o[mt][nt][3] * inv1);
        }
    }
}

// ---------------------------------------------------------------------------
// Output projection (fp16 mma): [16384,512] @ [512,64] + bias -> fp32
// ---------------------------------------------------------------------------
__global__ __launch_bounds__(256)
void out_gemm_kernel(const __half* __restrict__ z,
                     const __half* __restrict__ wt,
                     const float* __restrict__ bias,
                     float* __restrict__ out)
{
    extern __shared__ char smem_raw[];
    __half*   swt = (__half*)smem_raw;                       // [64][520]
    uint32_t* as  = (uint32_t*)(smem_raw + 64 * 520 * 2);    // 2 x 128 x 32 w

    const int tid  = threadIdx.x;
    const int warp = tid >> 5, lane = tid & 31;
    const int r = lane >> 2, qq = lane & 3;
    const int m0 = blockIdx.x * 128;

    const uint32_t wt_base = (uint32_t)__cvta_generic_to_shared(swt);
    const uint32_t as_base = (uint32_t)__cvta_generic_to_shared(as);

#define CPA(stage, kc) do {                                                   \
    _Pragma("unroll")                                                         \
    for (int it = 0; it < 4; it++) {                                          \
        int idx = tid + it * 256;                                             \
        int rr = idx >> 3, c4 = idx & 7;                                      \
        cp16(as_base + (uint32_t)((stage) * 16384 + rr * 128 +                \
                                  ((c4 ^ (rr & 7)) * 16)),                    \
             z + (size_t)(m0 + rr) * HD + (kc) * 64 + c4 * 8);                \
    }                                                                         \
    asm volatile("cp.async.commit_group;\n" ::);                              \
} while (0)

    #pragma unroll
    for (int it = 0; it < 16; it++) {
        int idx = tid + it * 256;
        int n = idx >> 6, c = idx & 63;
        cp16(wt_base + (uint32_t)(n * 1040 + c * 16), wt + n * 520 + c * 8);
    }
    CPA(0, 0);

    float acc[8][4] = {};

    for (int kc = 0; kc < 8; kc++) {
        const int s = kc & 1;
        if (kc < 7) {
            CPA(s ^ 1, kc + 1);
            asm volatile("cp.async.wait_group 1;\n" ::);
        } else {
            asm volatile("cp.async.wait_group 0;\n" ::);
        }
        __syncthreads();

        const uint32_t* asw = as + s * 4096;
        const int rowa0 = warp * 16 + r;
        const int rowa1 = rowa0 + 8;

        #pragma unroll
        for (int kt = 0; kt < 4; kt++) {
            uint32_t a[4];
            a[0] = asw[rowa0 * 32 + (((2*kt)   ^ r) << 2) + qq];
            a[1] = asw[rowa1 * 32 + (((2*kt)   ^ r) << 2) + qq];
            a[2] = asw[rowa0 * 32 + (((2*kt+1) ^ r) << 2) + qq];
            a[3] = asw[rowa1 * 32 + (((2*kt+1) ^ r) << 2) + qq];
            #pragma unroll
            for (int nt = 0; nt < 8; nt++) {
                int n = nt * 8 + r;
                const __half* wp = swt + n * 520 + kc * 64 + kt * 16 + 2 * qq;
                uint32_t b0 = *(const uint32_t*)wp;
                uint32_t b1 = *(const uint32_t*)(wp + 8);
                mma_f16(acc[nt], a, b0, b1);
            }
        }
        __syncthreads();
    }

    #pragma unroll
    for (int nt = 0; nt < 8; nt++) {
        int row0 = m0 + warp * 16 + r;
        int col  = nt * 8 + 2 * qq;
        float bx = bias[col], by = bias[col + 1];
        float2 v0 = {acc[nt][0] + bx, acc[nt][1] + by};
        float2 v1 = {acc[nt][2] + bx, acc[nt][3] + by};
        *(float2*)(out + (size_t)row0 * 64 + col)       = v0;
        *(float2*)(out + (size_t)(row0 + 8) * 64 + col) = v1;
    }
}

// ---------------------------------------------------------------------------
extern "C" void kernel_launch(void* const* d_in, const int* in_sizes, int n_in,
                              void* d_out, int out_size)
{
    const float* x    = (const float*)d_in[0];
    const float* Wqkv = (const float*)d_in[1];
    const float* Wout = (const float*)d_in[2];
    const float* bout = (const float*)d_in[3];
    float* out = (float*)d_out;

    __half *qp, *kp, *vtp, *zp, *wtp;
    cudaGetSymbolAddress((void**)&qp,  g_q);
    cudaGetSymbolAddress((void**)&kp,  g_k);
    cudaGetSymbolAddress((void**)&vtp, g_vt);
    cudaGetSymbolAddress((void**)&zp,  g_z);
    cudaGetSymbolAddress((void**)&wtp, g_wt);

    wconv_kernel<<<128, 256>>>(Wout, wtp);
    {
        dim3 grid(QKVN / 128, M_ / 64);
        qkv_gemm_kernel<<<grid, 256>>>(x, Wqkv, qp, kp, vtp);
    }
    {
        cudaFuncSetAttribute(attn_kernel,
                             cudaFuncAttributeMaxDynamicSharedMemorySize,
                             ATTN_SMEM);
        dim3 grid(N_ / 128, B_ * H_);
        attn_kernel<<<grid, 128, ATTN_SMEM>>>(qp, kp, vtp, zp);
    }
    {
        const int smem = 64 * 520 * 2 + 2 * 16384;   // 99328 B
        cudaFuncSetAttribute(out_gemm_kernel,
                             cudaFuncAttributeMaxDynamicSharedMemorySize, smem);
        out_gemm_kernel<<<M_ / 128, 256, smem>>>(zp, wtp, bout, out);
    }
}

// round 12
// speedup vs baseline: 1.6928x; 1.0150x over previous
#include <cuda_runtime.h>
#include <cuda_fp16.h>
#include <stdint.h>

#define B_   8
#define N_   2048
#define D_   64
#define H_   8
#define M_   (B_*N_)        // 16384
#define QKVN 1536
#define HD   512
#define QSCALE (0.125f * 1.44269504088896f)   // 1/sqrt(d) * log2(e)

// Scratch (__device__ globals; allocation-free rule)
__device__ __half g_q [(size_t)M_ * HD];
__device__ __half g_k [(size_t)M_ * HD];
__device__ __half g_vt[(size_t)B_*H_*D_*N_];      // [bh][d][tok]
__device__ __half g_z [(size_t)M_ * HD];
__device__ __half g_wt[64 * 520];                 // Wout^T fp16 [n][k]

// ---------------------------------------------------------------------------
// helpers
// ---------------------------------------------------------------------------
__device__ __forceinline__ uint32_t ex2h2(uint32_t x) {
    uint32_t y; asm("ex2.approx.f16x2 %0, %1;" : "=r"(y) : "r"(x)); return y;
}
__device__ __forceinline__ uint32_t packh2(float lo, float hi) {
    uint32_t u;
    asm("cvt.rn.f16x2.f32 %0, %1, %2;" : "=r"(u) : "f"(hi), "f"(lo));
    return u;
}
__device__ __forceinline__ void mma_f16(float d[4], const uint32_t a[4],
                                        uint32_t b0, uint32_t b1) {
    asm volatile(
        "mma.sync.aligned.m16n8k16.row.col.f32.f16.f16.f32 "
        "{%0,%1,%2,%3}, {%4,%5,%6,%7}, {%8,%9}, {%0,%1,%2,%3};\n"
        : "+f"(d[0]), "+f"(d[1]), "+f"(d[2]), "+f"(d[3])
        : "r"(a[0]), "r"(a[1]), "r"(a[2]), "r"(a[3]), "r"(b0), "r"(b1));
}
__device__ __forceinline__ void cp16(uint32_t dst_smem, const void* src) {
    asm volatile("cp.async.cg.shared.global [%0], [%1], 16;\n"
                 :: "r"(dst_smem), "l"(src));
}
__device__ __forceinline__ void ldsm_x4(uint32_t r[4], uint32_t addr) {
    asm volatile(
        "ldmatrix.sync.aligned.m8n8.x4.shared.b16 {%0,%1,%2,%3}, [%4];\n"
        : "=r"(r[0]), "=r"(r[1]), "=r"(r[2]), "=r"(r[3]) : "r"(addr));
}

// ---------------------------------------------------------------------------
// Wout fp32 [512][64] -> fp16 transposed [n][k] stride 520
// ---------------------------------------------------------------------------
__global__ __launch_bounds__(256)
void wconv_kernel(const float* __restrict__ W, __half* __restrict__ wt)
{
    int idx = blockIdx.x * 256 + threadIdx.x;
    int k = idx >> 6, n = idx & 63;
    wt[n * 520 + k] = __float2half_rn(W[idx]);
}

// ---------------------------------------------------------------------------
// QKV GEMM (fp16 mma): [16384,64] @ [64,1536]
// Block 64(m) x 128(n), 256 threads, warp tile 16x64.
// ---------------------------------------------------------------------------
__global__ __launch_bounds__(256)
void qkv_gemm_kernel(const float* __restrict__ x,
                     const float* __restrict__ W,
                     __half* __restrict__ q,
                     __half* __restrict__ kk,
                     __half* __restrict__ vt)
{
    __shared__ __align__(16) char smem_u[128 * 72 * 2];
    __half (*Wt)[72] = (__half(*)[72])smem_u;              // [n][k]
    __half (*sv)[72] = (__half(*)[72])smem_u;              // [col][tok] (V)

    const int tid  = threadIdx.x;
    const int warp = tid >> 5, lane = tid & 31;
    const int r = lane >> 2, qq = lane & 3;
    const int wm = warp >> 1, wn = warp & 1;
    const int n0 = blockIdx.x * 128;
    const int m0 = blockIdx.y * 64;

    #pragma unroll
    for (int it = 0; it < 8; it++) {
        int idx = tid + it * 256;
        int kw = idx >> 5;
        int c4 = idx & 31;
        float4 w = *(const float4*)(W + (size_t)kw * QKVN + n0 + c4 * 4);
        Wt[c4 * 4 + 0][kw] = __float2half_rn(w.x);
        Wt[c4 * 4 + 1][kw] = __float2half_rn(w.y);
        Wt[c4 * 4 + 2][kw] = __float2half_rn(w.z);
        Wt[c4 * 4 + 3][kw] = __float2half_rn(w.w);
    }

    uint32_t qa[4][4];
    {
        const float* p0 = x + (size_t)(m0 + wm * 16 + r) * 64;
        const float* p1 = p0 + 8 * 64;
        #pragma unroll
        for (int kt = 0; kt < 4; kt++) {
            int c = kt * 16 + 2 * qq;
            float2 a0 = *(const float2*)(p0 + c);
            float2 a1 = *(const float2*)(p1 + c);
            float2 a2 = *(const float2*)(p0 + c + 8);
            float2 a3 = *(const float2*)(p1 + c + 8);
            qa[kt][0] = packh2(a0.x, a0.y);
            qa[kt][1] = packh2(a1.x, a1.y);
            qa[kt][2] = packh2(a2.x, a2.y);
            qa[kt][3] = packh2(a3.x, a3.y);
        }
    }
    __syncthreads();

    float acc[8][4] = {};
    #pragma unroll
    for (int kt = 0; kt < 4; kt++) {
        #pragma unroll
        for (int nt = 0; nt < 8; nt++) {
            int n = wn * 64 + nt * 8 + r;
            uint32_t b0 = *(const uint32_t*)&Wt[n][kt * 16 + 2 * qq];
            uint32_t b1 = *(const uint32_t*)&Wt[n][kt * 16 + 2 * qq + 8];
            mma_f16(acc[nt], qa[kt], b0, b1);
        }
    }

    if (n0 < 1024) {
        const float s = (n0 < 512) ? QSCALE : 1.0f;
        __half* dst = (n0 < 512) ? q : kk;
        const int cbase = (n0 < 512) ? n0 : (n0 - 512);
        #pragma unroll
        for (int nt = 0; nt < 8; nt++) {
            int row0 = m0 + wm * 16 + r;
            int col  = cbase + wn * 64 + nt * 8 + 2 * qq;
            *(uint32_t*)(dst + (size_t)row0 * HD + col) =
                packh2(acc[nt][0] * s, acc[nt][1] * s);
            *(uint32_t*)(dst + (size_t)(row0 + 8) * HD + col) =
                packh2(acc[nt][2] * s, acc[nt][3] * s);
        }
    } else {
        __syncthreads();
        #pragma unroll
        for (int nt = 0; nt < 8; nt++) {
            int row_l = wm * 16 + r;
            int col_l = wn * 64 + nt * 8 + 2 * qq;
            sv[col_l    ][row_l]     = __float2half_rn(acc[nt][0]);
            sv[col_l + 1][row_l]     = __float2half_rn(acc[nt][1]);
            sv[col_l    ][row_l + 8] = __float2half_rn(acc[nt][2]);
            sv[col_l + 1][row_l + 8] = __float2half_rn(acc[nt][3]);
        }
        __syncthreads();
        const int h0   = (n0 - 1024) >> 6;
        const int b    = m0 >> 11;
        const int tok0 = m0 & 2047;
        #pragma unroll
        for (int it = 0; it < 4; it++) {
            int idx = tid + it * 256;
            int col = idx >> 3, c8 = idx & 7;
            uint4 v = *(uint4*)&sv[col][c8 * 8];
            int h = h0 + (col >> 6), d = col & 63;
            *(uint4*)(vt + ((size_t)((b * 8 + h) * 64 + d)) * N_ +
                      tok0 + c8 * 8) = v;
        }
    }
}

// ---------------------------------------------------------------------------
// Flash attention: 128 threads / 4 warps, warp = 32 q rows, LDSM fragments,
// 3-stage cp.async ring, frozen offset FOLDED INTO the S accumulator init;
// tile 0 peeled.
// ---------------------------------------------------------------------------
#define VSTRIDE 88
#define KS_STAGE 8192
#define VS_STAGE (64 * VSTRIDE * 2)          // 11264
#define ATTN_SMEM (3 * (KS_STAGE + VS_STAGE))
#define NTILES (N_ / 64)

__global__ __launch_bounds__(128)
void attn_kernel(const __half* __restrict__ q,
                 const __half* __restrict__ kglb,
                 const __half* __restrict__ vt,
                 __half* __restrict__ z)
{
    extern __shared__ __align__(16) char smem_raw[];

    const int tid  = threadIdx.x;
    const int warp = tid >> 5, lane = tid & 31;
    const int r = lane >> 2, qq = lane & 3;
    const int lrow = lane & 7;
    const int ltile = lane >> 3;
    const int bh = blockIdx.y;
    const int b = bh >> 3, h = bh & 7;
    const int q0 = blockIdx.x * 128 + warp * 32;
    const uint32_t ONE2 = 0x3C003C00u;

    uint32_t qa[2][4][4];
    #pragma unroll
    for (int mt = 0; mt < 2; mt++) {
        const __half* p0 = q + (size_t)(b * N_ + q0 + mt * 16 + r) * HD + h * D_;
        const __half* p1 = p0 + 8 * (size_t)HD;
        #pragma unroll
        for (int kt = 0; kt < 4; kt++) {
            int c = kt * 16 + 2 * qq;
            qa[mt][kt][0] = *(const uint32_t*)(p0 + c);
            qa[mt][kt][1] = *(const uint32_t*)(p1 + c);
            qa[mt][kt][2] = *(const uint32_t*)(p0 + c + 8);
            qa[mt][kt][3] = *(const uint32_t*)(p1 + c + 8);
        }
    }

    float o[2][8][4] = {};
    float lf[2][4] = {};
    float nm[2][2];                       // NEGATIVE frozen offsets

    const __half* kb = kglb + (size_t)(b * N_) * HD + h * D_;
    const __half* vb = vt + (size_t)bh * D_ * N_;

    const uint32_t ks_base = (uint32_t)__cvta_generic_to_shared(smem_raw);
    const uint32_t vs_base = ks_base + 3 * KS_STAGE;

    const uint32_t kx0 = (uint32_t)(((0 * 4 + ltile) ^ lrow) * 16) + lrow * 128;
    const uint32_t kx1 = (uint32_t)(((1 * 4 + ltile) ^ lrow) * 16) + lrow * 128;
    const uint32_t vx  = (uint32_t)((lrow * VSTRIDE + ltile * 8) * 2);

#define CP_TILE(stage, j0) do {                                               \
    _Pragma("unroll")                                                         \
    for (int it = 0; it < 4; it++) {                                          \
        int idx = tid + it * 128;                                             \
        int rr = idx >> 3, c4 = idx & 7;                                      \
        cp16(ks_base + (uint32_t)((stage) * KS_STAGE + rr * 128 +             \
                                  ((c4 ^ (rr & 7)) * 16)),                    \
             kb + (size_t)((j0) + rr) * HD + c4 * 8);                         \
    }                                                                         \
    _Pragma("unroll")                                                         \
    for (int it = 0; it < 4; it++) {                                          \
        int idx = tid + it * 128;                                             \
        int dd = idx >> 3, c8 = idx & 7;                                      \
        cp16(vs_base + (uint32_t)((stage) * VS_STAGE +                        \
                                  (dd * VSTRIDE + c8 * 8) * 2),               \
             vb + (size_t)dd * N_ + (j0) + c8 * 8);                           \
    }                                                                         \
    asm volatile("cp.async.commit_group;\n" ::);                              \
} while (0)

// S-MMA phase for one tile (accumulator pre-initialized in sc)
#define S_PHASE(ksb_) do {                                                    \
    _Pragma("unroll")                                                         \
    for (int ktp = 0; ktp < 2; ktp++) {                                       \
        const uint32_t kx = ktp ? kx1 : kx0;                                  \
        _Pragma("unroll")                                                     \
        for (int nt = 0; nt < 8; nt++) {                                      \
            uint32_t kbf[4];                                                  \
            ldsm_x4(kbf, (ksb_) + nt * 1024 + kx);                            \
            mma_f16(sc[0][nt], qa[0][2*ktp],   kbf[0], kbf[1]);               \
            mma_f16(sc[1][nt], qa[1][2*ktp],   kbf[0], kbf[1]);               \
            mma_f16(sc[0][nt], qa[0][2*ktp+1], kbf[2], kbf[3]);               \
            mma_f16(sc[1][nt], qa[1][2*ktp+1], kbf[2], kbf[3]);               \
        }                                                                     \
    }                                                                         \
} while (0)

// PV + l phase for one tile (pl/ph hold P fragments)
#define PV_PHASE(vsb_) do {                                                   \
    _Pragma("unroll")                                                         \
    for (int ktp = 0; ktp < 2; ktp++) {                                       \
        uint32_t paA[2][4], paB[2][4];                                        \
        _Pragma("unroll")                                                     \
        for (int mt = 0; mt < 2; mt++) {                                      \
            paA[mt][0] = pl[mt][4*ktp + 0];                                   \
            paA[mt][1] = ph[mt][4*ktp + 0];                                   \
            paA[mt][2] = pl[mt][4*ktp + 1];                                   \
            paA[mt][3] = ph[mt][4*ktp + 1];                                   \
            paB[mt][0] = pl[mt][4*ktp + 2];                                   \
            paB[mt][1] = ph[mt][4*ktp + 2];                                   \
            paB[mt][2] = pl[mt][4*ktp + 3];                                   \
            paB[mt][3] = ph[mt][4*ktp + 3];                                   \
        }                                                                     \
        _Pragma("unroll")                                                     \
        for (int nt = 0; nt < 8; nt++) {                                      \
            uint32_t vbf[4];                                                  \
            ldsm_x4(vbf, (vsb_) + nt * (8 * VSTRIDE * 2) + ktp * 64 + vx);    \
            mma_f16(o[0][nt], paA[0], vbf[0], vbf[1]);                        \
            mma_f16(o[1][nt], paA[1], vbf[0], vbf[1]);                        \
            mma_f16(o[0][nt], paB[0], vbf[2], vbf[3]);                        \
            mma_f16(o[1][nt], paB[1], vbf[2], vbf[3]);                        \
        }                                                                     \
        mma_f16(lf[0], paA[0], ONE2, ONE2);                                   \
        mma_f16(lf[1], paA[1], ONE2, ONE2);                                   \
        mma_f16(lf[0], paB[0], ONE2, ONE2);                                   \
        mma_f16(lf[1], paB[1], ONE2, ONE2);                                   \
    }                                                                         \
} while (0)

    CP_TILE(0, 0);
    CP_TILE(1, 64);

    // ================= tile 0 (peeled): raw S, compute frozen offset ========
    {
        asm volatile("cp.async.wait_group 1;\n" ::);
        __syncthreads();
        CP_TILE(2, 128);

        float sc[2][8][4] = {};
        uint32_t pl[2][8], ph[2][8];
        S_PHASE(ks_base);

        #pragma unroll
        for (int mt = 0; mt < 2; mt++) {
            float mx0 = -1e30f, mx1 = -1e30f;
            #pragma unroll
            for (int nt = 0; nt < 8; nt++) {
                mx0 = fmaxf(mx0, fmaxf(sc[mt][nt][0], sc[mt][nt][1]));
                mx1 = fmaxf(mx1, fmaxf(sc[mt][nt][2], sc[mt][nt][3]));
            }
            mx0 = fmaxf(mx0, __shfl_xor_sync(0xffffffffu, mx0, 1));
            mx0 = fmaxf(mx0, __shfl_xor_sync(0xffffffffu, mx0, 2));
            mx1 = fmaxf(mx1, __shfl_xor_sync(0xffffffffu, mx1, 1));
            mx1 = fmaxf(mx1, __shfl_xor_sync(0xffffffffu, mx1, 2));
            nm[mt][0] = -mx0;
            nm[mt][1] = -mx1;
            #pragma unroll
            for (int nt = 0; nt < 8; nt++) {
                pl[mt][nt] = ex2h2(packh2(sc[mt][nt][0] + nm[mt][0],
                                          sc[mt][nt][1] + nm[mt][0]));
                ph[mt][nt] = ex2h2(packh2(sc[mt][nt][2] + nm[mt][1],
                                          sc[mt][nt][3] + nm[mt][1]));
            }
        }
        PV_PHASE(vs_base);
    }

    // ================= tiles 1..NTILES-1: offset folded into accumulator ====
    int st = 1;
    for (int t = 1; t < NTILES; t++) {
        if (t < NTILES - 1) {
            asm volatile("cp.async.wait_group 1;\n" ::);
        } else {
            asm volatile("cp.async.wait_group 0;\n" ::);
        }
        __syncthreads();

        const uint32_t ksb = ks_base + st * KS_STAGE;
        const uint32_t vsb = vs_base + st * VS_STAGE;

        // S accumulators pre-seeded with -m  ->  MMA output IS (s - m)
        float sc[2][8][4];
        #pragma unroll
        for (int mt = 0; mt < 2; mt++)
            #pragma unroll
            for (int nt = 0; nt < 8; nt++) {
                sc[mt][nt][0] = nm[mt][0];
                sc[mt][nt][1] = nm[mt][0];
                sc[mt][nt][2] = nm[mt][1];
                sc[mt][nt][3] = nm[mt][1];
            }

        S_PHASE(ksb);

        // prefetch AFTER compute has started consuming this stage
        if (t + 2 < NTILES) {
            int st2 = st + 2; if (st2 >= 3) st2 -= 3;
            CP_TILE(st2, (t + 2) * 64);
        }

        // P = exp2(sc) straight away (no subtraction needed)
        uint32_t pl[2][8], ph[2][8];
        #pragma unroll
        for (int mt = 0; mt < 2; mt++) {
            #pragma unroll
            for (int nt = 0; nt < 8; nt++) {
                pl[mt][nt] = ex2h2(packh2(sc[mt][nt][0], sc[mt][nt][1]));
                ph[mt][nt] = ex2h2(packh2(sc[mt][nt][2], sc[mt][nt][3]));
            }
        }

        PV_PHASE(vsb);

        st++; if (st >= 3) st -= 3;
    }

    // ---- finalize ----
    #pragma unroll
    for (int mt = 0; mt < 2; mt++) {
        float inv0 = 1.f / lf[mt][0];
        float inv1 = 1.f / lf[mt][2];
        int row0 = q0 + mt * 16 + r;
        __half* zp0 = z + (size_t)(b * N_ + row0) * HD + h * D_;
        __half* zp1 = zp0 + 8 * (size_t)HD;
        #pragma unroll
        for (int nt = 0; nt < 8; nt++) {
            int col = nt * 8 + 2 * qq;
            *(uint32_t*)(zp0 + col) = packh2(o[mt][nt][0] * inv0,
                                             o[mt][nt][1] * inv0);
            *(uint32_t*)(zp1 + col) = packh2(o[mt][nt][2] * inv1,
                                             o[mt][nt][3] * inv1);
        }
    }
}

// ---------------------------------------------------------------------------
// Output projection (fp16 mma): [16384,512] @ [512,64] + bias -> fp32
// ---------------------------------------------------------------------------
__global__ __launch_bounds__(256)
void out_gemm_kernel(const __half* __restrict__ z,
                     const __half* __restrict__ wt,
                     const float* __restrict__ bias,
                     float* __restrict__ out)
{
    extern __shared__ char smem_raw[];
    __half*   swt = (__half*)smem_raw;                       // [64][520]
    uint32_t* as  = (uint32_t*)(smem_raw + 64 * 520 * 2);    // 2 x 128 x 32 w

    const int tid  = threadIdx.x;
    const int warp = tid >> 5, lane = tid & 31;
    const int r = lane >> 2, qq = lane & 3;
    const int m0 = blockIdx.x * 128;

    const uint32_t wt_base = (uint32_t)__cvta_generic_to_shared(swt);
    const uint32_t as_base = (uint32_t)__cvta_generic_to_shared(as);

#define CPA(stage, kc) do {                                                   \
    _Pragma("unroll")                                                         \
    for (int it = 0; it < 4; it++) {                                          \
        int idx = tid + it * 256;                                             \
        int rr = idx >> 3, c4 = idx & 7;                                      \
        cp16(as_base + (uint32_t)((stage) * 16384 + rr * 128 +                \
                                  ((c4 ^ (rr & 7)) * 16)),                    \
             z + (size_t)(m0 + rr) * HD + (kc) * 64 + c4 * 8);                \
    }                                                                         \
    asm volatile("cp.async.commit_group;\n" ::);                              \
} while (0)

    #pragma unroll
    for (int it = 0; it < 16; it++) {
        int idx = tid + it * 256;
        int n = idx >> 6, c = idx & 63;
        cp16(wt_base + (uint32_t)(n * 1040 + c * 16), wt + n * 520 + c * 8);
    }
    CPA(0, 0);

    float acc[8][4] = {};

    for (int kc = 0; kc < 8; kc++) {
        const int s = kc & 1;
        if (kc < 7) {
            CPA(s ^ 1, kc + 1);
            asm volatile("cp.async.wait_group 1;\n" ::);
        } else {
            asm volatile("cp.async.wait_group 0;\n" ::);
        }
        __syncthreads();

        const uint32_t* asw = as + s * 4096;
        const int rowa0 = warp * 16 + r;
        const int rowa1 = rowa0 + 8;

        #pragma unroll
        for (int kt = 0; kt < 4; kt++) {
            uint32_t a[4];
            a[0] = asw[rowa0 * 32 + (((2*kt)   ^ r) << 2) + qq];
            a[1] = asw[rowa1 * 32 + (((2*kt)   ^ r) << 2) + qq];
            a[2] = asw[rowa0 * 32 + (((2*kt+1) ^ r) << 2) + qq];
            a[3] = asw[rowa1 * 32 + (((2*kt+1) ^ r) << 2) + qq];
            #pragma unroll
            for (int nt = 0; nt < 8; nt++) {
                int n = nt * 8 + r;
                const __half* wp = swt + n * 520 + kc * 64 + kt * 16 + 2 * qq;
                uint32_t b0 = *(const uint32_t*)wp;
                uint32_t b1 = *(const uint32_t*)(wp + 8);
                mma_f16(acc[nt], a, b0, b1);
            }
        }
        __syncthreads();
    }

    #pragma unroll
    for (int nt = 0; nt < 8; nt++) {
        int row0 = m0 + warp * 16 + r;
        int col  = nt * 8 + 2 * qq;
        float bx = bias[col], by = bias[col + 1];
        float2 v0 = {acc[nt][0] + bx, acc[nt][1] + by};
        float2 v1 = {acc[nt][2] + bx, acc[nt][3] + by};
        *(float2*)(out + (size_t)row0 * 64 + col)       = v0;
        *(float2*)(out + (size_t)(row0 + 8) * 64 + col) = v1;
    }
}

// ---------------------------------------------------------------------------
extern "C" void kernel_launch(void* const* d_in, const int* in_sizes, int n_in,
                              void* d_out, int out_size)
{
    const float* x    = (const float*)d_in[0];
    const float* Wqkv = (const float*)d_in[1];
    const float* Wout = (const float*)d_in[2];
    const float* bout = (const float*)d_in[3];
    float* out = (float*)d_out;

    __half *qp, *kp, *vtp, *zp, *wtp;
    cudaGetSymbolAddress((void**)&qp,  g_q);
    cudaGetSymbolAddress((void**)&kp,  g_k);
    cudaGetSymbolAddress((void**)&vtp, g_vt);
    cudaGetSymbolAddress((void**)&zp,  g_z);
    cudaGetSymbolAddress((void**)&wtp, g_wt);

    wconv_kernel<<<128, 256>>>(Wout, wtp);
    {
        dim3 grid(QKVN / 128, M_ / 64);
        qkv_gemm_kernel<<<grid, 256>>>(x, Wqkv, qp, kp, vtp);
    }
    {
        cudaFuncSetAttribute(attn_kernel,
                             cudaFuncAttributeMaxDynamicSharedMemorySize,
                             ATTN_SMEM);
        dim3 grid(N_ / 128, B_ * H_);
        attn_kernel<<<grid, 128, ATTN_SMEM>>>(qp, kp, vtp, zp);
    }
    {
        const int smem = 64 * 520 * 2 + 2 * 16384;   // 99328 B
        cudaFuncSetAttribute(out_gemm_kernel,
                             cudaFuncAttributeMaxDynamicSharedMemorySize, smem);
        out_gemm_kernel<<<M_ / 128, 256, smem>>>(zp, wtp, bout, out);
    }
}

// round 14
// speedup vs baseline: 2.0868x; 1.2328x over previous
#include <cuda_runtime.h>
#include <cuda_fp16.h>
#include <stdint.h>

#define B_   8
#define N_   2048
#define D_   64
#define H_   8
#define M_   (B_*N_)        // 16384
#define QKVN 1536
#define HD   512
#define QSCALE (0.125f * 1.44269504088896f)   // 1/sqrt(d) * log2(e)

// Scratch (__device__ globals; allocation-free rule)
__device__ __half g_q [(size_t)M_ * HD];
__device__ __half g_k [(size_t)M_ * HD];
__device__ __half g_vt[(size_t)B_*H_*D_*N_];      // [bh][d][tok]
__device__ __half g_z [(size_t)M_ * HD];
__device__ __half g_wt[64 * 520];                 // Wout^T fp16 [n][k]
__device__ __half g_wq[12 * 128 * 64];            // Wqkv^T fp16 [tile][n][k]

// ---------------------------------------------------------------------------
// helpers
// ---------------------------------------------------------------------------
__device__ __forceinline__ uint32_t ex2h2(uint32_t x) {
    uint32_t y; asm("ex2.approx.f16x2 %0, %1;" : "=r"(y) : "r"(x)); return y;
}
__device__ __forceinline__ uint32_t packh2(float lo, float hi) {
    uint32_t u;
    asm("cvt.rn.f16x2.f32 %0, %1, %2;" : "=r"(u) : "f"(hi), "f"(lo));
    return u;
}
__device__ __forceinline__ void mma_f16(float d[4], const uint32_t a[4],
                                        uint32_t b0, uint32_t b1) {
    asm volatile(
        "mma.sync.aligned.m16n8k16.row.col.f32.f16.f16.f32 "
        "{%0,%1,%2,%3}, {%4,%5,%6,%7}, {%8,%9}, {%0,%1,%2,%3};\n"
        : "+f"(d[0]), "+f"(d[1]), "+f"(d[2]), "+f"(d[3])
        : "r"(a[0]), "r"(a[1]), "r"(a[2]), "r"(a[3]), "r"(b0), "r"(b1));
}
__device__ __forceinline__ void cp16(uint32_t dst_smem, const void* src) {
    asm volatile("cp.async.cg.shared.global [%0], [%1], 16;\n"
                 :: "r"(dst_smem), "l"(src));
}
__device__ __forceinline__ void ldsm_x4(uint32_t r[4], uint32_t addr) {
    asm volatile(
        "ldmatrix.sync.aligned.m8n8.x4.shared.b16 {%0,%1,%2,%3}, [%4];\n"
        : "=r"(r[0]), "=r"(r[1]), "=r"(r[2]), "=r"(r[3]) : "r"(addr));
}

// ---------------------------------------------------------------------------
// prep: Wqkv [64][1536] -> g_wq [12][128][64] fp16 (transposed, tile-major)
//       Wout [512][64]  -> g_wt [64][520]     fp16 (transposed)
// ---------------------------------------------------------------------------
__global__ __launch_bounds__(256)
void prep_kernel(const float* __restrict__ Wqkv, const float* __restrict__ Wout,
                 __half* __restrict__ wq, __half* __restrict__ wt)
{
    int idx = blockIdx.x * 256 + threadIdx.x;          // 0 .. 131071
    if (idx < 98304) {
        int k = idx / QKVN;            // 0..63
        int n = idx - k * QKVN;        // 0..1535 (coalesced read)
        wq[(size_t)(n >> 7) * 8192 + (n & 127) * 64 + k] =
            __float2half_rn(Wqkv[idx]);
    } else {
        int j = idx - 98304;           // 0..32767
        int k = j >> 6, n = j & 63;
        wt[n * 520 + k] = __float2half_rn(Wout[j]);
    }
}

// ---------------------------------------------------------------------------
// QKV GEMM (fp16 mma, persistent over n): [16384,64] @ [64,1536]
// 256 blocks (one 64-row m-tile each), 256 threads / 8 warps.
// x A-frags loaded ONCE; W fp16 streamed via 3-stage cp.async ring.
// ---------------------------------------------------------------------------
#define WST 18432                       // stage: 128 rows x 144 B
#define QKV_SMEM (3 * WST + 18432)      // + sv transpose buffer = 73728 B

__global__ __launch_bounds__(256)
void qkv_gemm_kernel(const float* __restrict__ x,
                     const __half* __restrict__ wq,
                     __half* __restrict__ q,
                     __half* __restrict__ kk,
                     __half* __restrict__ vt)
{
    extern __shared__ __align__(16) char smem_raw[];
    __half (*sv)[72] = (__half(*)[72])(smem_raw + 3 * WST);

    const int tid  = threadIdx.x;
    const int warp = tid >> 5, lane = tid & 31;
    const int r = lane >> 2, qq = lane & 3;
    const int wm = warp >> 1, wn = warp & 1;
    const int m0 = blockIdx.x * 64;

    const uint32_t sb = (uint32_t)__cvta_generic_to_shared(smem_raw);

#define CPW(stg, tn_) do {                                                    \
    _Pragma("unroll")                                                         \
    for (int it = 0; it < 4; it++) {                                          \
        int idx = tid + it * 256;                                             \
        int n = idx >> 3, c = idx & 7;                                        \
        cp16(sb + (uint32_t)((stg) * WST + n * 144 + c * 16),                 \
             wq + (size_t)(tn_) * 8192 + n * 64 + c * 8);                     \
    }                                                                         \
    asm volatile("cp.async.commit_group;\n" ::);                              \
} while (0)

    CPW(0, 0);
    CPW(1, 1);

    // x A-frags, loaded once (float2 -> packed fp16)
    uint32_t qa[4][4];
    {
        const float* p0 = x + (size_t)(m0 + wm * 16 + r) * 64;
        const float* p1 = p0 + 8 * 64;
        #pragma unroll
        for (int kt = 0; kt < 4; kt++) {
            int c = kt * 16 + 2 * qq;
            float2 a0 = *(const float2*)(p0 + c);
            float2 a1 = *(const float2*)(p1 + c);
            float2 a2 = *(const float2*)(p0 + c + 8);
            float2 a3 = *(const float2*)(p1 + c + 8);
            qa[kt][0] = packh2(a0.x, a0.y);
            qa[kt][1] = packh2(a1.x, a1.y);
            qa[kt][2] = packh2(a2.x, a2.y);
            qa[kt][3] = packh2(a3.x, a3.y);
        }
    }

    int st = 0;
    #pragma unroll 1
    for (int tn = 0; tn < 12; tn++) {
        if (tn < 11) { asm volatile("cp.async.wait_group 1;\n" ::); }
        else         { asm volatile("cp.async.wait_group 0;\n" ::); }
        __syncthreads();

        if (tn + 2 < 12) {
            int st2 = st + 2; if (st2 >= 3) st2 -= 3;
            CPW(st2, tn + 2);
        }

        const uint32_t wst = sb + st * WST;

        float acc[8][4] = {};
        #pragma unroll
        for (int kt = 0; kt < 4; kt++) {
            #pragma unroll
            for (int nt = 0; nt < 8; nt++) {
                int n = wn * 64 + nt * 8 + r;
                uint32_t addr = wst + n * 144 + (kt * 16 + 2 * qq) * 2;
                uint32_t b0, b1;
                asm volatile("ld.shared.b32 %0, [%1];" : "=r"(b0) : "r"(addr));
                asm volatile("ld.shared.b32 %0, [%1];" : "=r"(b1) : "r"(addr + 16));
                mma_f16(acc[nt], qa[kt], b0, b1);
            }
        }

        const int n0 = tn * 128;
        if (n0 < 1024) {
            const float s = (n0 < 512) ? QSCALE : 1.0f;
            __half* dst = (n0 < 512) ? q : kk;
            const int cbase = (n0 < 512) ? n0 : (n0 - 512);
            #pragma unroll
            for (int nt = 0; nt < 8; nt++) {
                int row0 = m0 + wm * 16 + r;
                int col  = cbase + wn * 64 + nt * 8 + 2 * qq;
                *(uint32_t*)(dst + (size_t)row0 * HD + col) =
                    packh2(acc[nt][0] * s, acc[nt][1] * s);
                *(uint32_t*)(dst + (size_t)(row0 + 8) * HD + col) =
                    packh2(acc[nt][2] * s, acc[nt][3] * s);
            }
        } else {
            // V: transpose via smem, then coalesced STG.128
            #pragma unroll
            for (int nt = 0; nt < 8; nt++) {
                int row_l = wm * 16 + r;
                int col_l = wn * 64 + nt * 8 + 2 * qq;
                sv[col_l    ][row_l]     = __float2half_rn(acc[nt][0]);
                sv[col_l + 1][row_l]     = __float2half_rn(acc[nt][1]);
                sv[col_l    ][row_l + 8] = __float2half_rn(acc[nt][2]);
                sv[col_l + 1][row_l + 8] = __float2half_rn(acc[nt][3]);
            }
            __syncthreads();
            const int h0   = (n0 - 1024) >> 6;
            const int b    = m0 >> 11;
            const int tok0 = m0 & 2047;
            #pragma unroll
            for (int it = 0; it < 4; it++) {
                int idx = tid + it * 256;
                int col = idx >> 3, c8 = idx & 7;
                uint4 v = *(uint4*)&sv[col][c8 * 8];
                int h = h0 + (col >> 6), d = col & 63;
                *(uint4*)(vt + ((size_t)((b * 8 + h) * 64 + d)) * N_ +
                          tok0 + c8 * 8) = v;
            }
        }

        st++; if (st >= 3) st -= 3;
    }
}

// ---------------------------------------------------------------------------
// Flash attention (R12 best): 128 threads / 4 warps, warp = 32 q rows, LDSM,
// 3-stage cp.async ring, frozen offset folded into S accumulator init.
// ---------------------------------------------------------------------------
#define VSTRIDE 88
#define KS_STAGE 8192
#define VS_STAGE (64 * VSTRIDE * 2)          // 11264
#define ATTN_SMEM (3 * (KS_STAGE + VS_STAGE))
#define NTILES (N_ / 64)

__global__ __launch_bounds__(128)
void attn_kernel(const __half* __restrict__ q,
                 const __half* __restrict__ kglb,
                 const __half* __restrict__ vt,
                 __half* __restrict__ z)
{
    extern __shared__ __align__(16) char smem_raw[];

    const int tid  = threadIdx.x;
    const int warp = tid >> 5, lane = tid & 31;
    const int r = lane >> 2, qq = lane & 3;
    const int lrow = lane & 7;
    const int ltile = lane >> 3;
    const int bh = blockIdx.y;
    const int b = bh >> 3, h = bh & 7;
    const int q0 = blockIdx.x * 128 + warp * 32;
    const uint32_t ONE2 = 0x3C003C00u;

    uint32_t qa[2][4][4];
    #pragma unroll
    for (int mt = 0; mt < 2; mt++) {
        const __half* p0 = q + (size_t)(b * N_ + q0 + mt * 16 + r) * HD + h * D_;
        const __half* p1 = p0 + 8 * (size_t)HD;
        #pragma unroll
        for (int kt = 0; kt < 4; kt++) {
            int c = kt * 16 + 2 * qq;
            qa[mt][kt][0] = *(const uint32_t*)(p0 + c);
            qa[mt][kt][1] = *(const uint32_t*)(p1 + c);
            qa[mt][kt][2] = *(const uint32_t*)(p0 + c + 8);
            qa[mt][kt][3] = *(const uint32_t*)(p1 + c + 8);
        }
    }

    float o[2][8][4] = {};
    float lf[2][4] = {};
    float nm[2][2];                       // NEGATIVE frozen offsets

    const __half* kb = kglb + (size_t)(b * N_) * HD + h * D_;
    const __half* vb = vt + (size_t)bh * D_ * N_;

    const uint32_t ks_base = (uint32_t)__cvta_generic_to_shared(smem_raw);
    const uint32_t vs_base = ks_base + 3 * KS_STAGE;

    const uint32_t kx0 = (uint32_t)(((0 * 4 + ltile) ^ lrow) * 16) + lrow * 128;
    const uint32_t kx1 = (uint32_t)(((1 * 4 + ltile) ^ lrow) * 16) + lrow * 128;
    const uint32_t vx  = (uint32_t)((lrow * VSTRIDE + ltile * 8) * 2);

#define CP_TILE(stage, j0) do {                                               \
    _Pragma("unroll")                                                         \
    for (int it = 0; it < 4; it++) {                                          \
        int idx = tid + it * 128;                                             \
        int rr = idx >> 3, c4 = idx & 7;                                      \
        cp16(ks_base + (uint32_t)((stage) * KS_STAGE + rr * 128 +             \
                                  ((c4 ^ (rr & 7)) * 16)),                    \
             kb + (size_t)((j0) + rr) * HD + c4 * 8);                         \
    }                                                                         \
    _Pragma("unroll")                                                         \
    for (int it = 0; it < 4; it++) {                                          \
        int idx = tid + it * 128;                                             \
        int dd = idx >> 3, c8 = idx & 7;                                      \
        cp16(vs_base + (uint32_t)((stage) * VS_STAGE +                        \
                                  (dd * VSTRIDE + c8 * 8) * 2),               \
             vb + (size_t)dd * N_ + (j0) + c8 * 8);                           \
    }                                                                         \
    asm volatile("cp.async.commit_group;\n" ::);                              \
} while (0)

#define S_PHASE(ksb_) do {                                                    \
    _Pragma("unroll")                                                         \
    for (int ktp = 0; ktp < 2; ktp++) {                                       \
        const uint32_t kx = ktp ? kx1 : kx0;                                  \
        _Pragma("unroll")                                                     \
        for (int nt = 0; nt < 8; nt++) {                                      \
            uint32_t kbf[4];                                                  \
            ldsm_x4(kbf, (ksb_) + nt * 1024 + kx);                            \
            mma_f16(sc[0][nt], qa[0][2*ktp],   kbf[0], kbf[1]);               \
            mma_f16(sc[1][nt], qa[1][2*ktp],   kbf[0], kbf[1]);               \
            mma_f16(sc[0][nt], qa[0][2*ktp+1], kbf[2], kbf[3]);               \
            mma_f16(sc[1][nt], qa[1][2*ktp+1], kbf[2], kbf[3]);               \
        }                                                                     \
    }                                                                         \
} while (0)

#define PV_PHASE(vsb_) do {                                                   \
    _Pragma("unroll")                                                         \
    for (int ktp = 0; ktp < 2; ktp++) {                                       \
        uint32_t paA[2][4], paB[2][4];                                        \
        _Pragma("unroll")                                                     \
        for (int mt = 0; mt < 2; mt++) {                                      \
            paA[mt][0] = pl[mt][4*ktp + 0];                                   \
            paA[mt][1] = ph[mt][4*ktp + 0];                                   \
            paA[mt][2] = pl[mt][4*ktp + 1];                                   \
            paA[mt][3] = ph[mt][4*ktp + 1];                                   \
            paB[mt][0] = pl[mt][4*ktp + 2];                                   \
            paB[mt][1] = ph[mt][4*ktp + 2];                                   \
            paB[mt][2] = pl[mt][4*ktp + 3];                                   \
            paB[mt][3] = ph[mt][4*ktp + 3];                                   \
        }                                                                     \
        _Pragma("unroll")                                                     \
        for (int nt = 0; nt < 8; nt++) {                                      \
            uint32_t vbf[4];                                                  \
            ldsm_x4(vbf, (vsb_) + nt * (8 * VSTRIDE * 2) + ktp * 64 + vx);    \
            mma_f16(o[0][nt], paA[0], vbf[0], vbf[1]);                        \
            mma_f16(o[1][nt], paA[1], vbf[0], vbf[1]);                        \
            mma_f16(o[0][nt], paB[0], vbf[2], vbf[3]);                        \
            mma_f16(o[1][nt], paB[1], vbf[2], vbf[3]);                        \
        }                                                                     \
        mma_f16(lf[0], paA[0], ONE2, ONE2);                                   \
        mma_f16(lf[1], paA[1], ONE2, ONE2);                                   \
        mma_f16(lf[0], paB[0], ONE2, ONE2);                                   \
        mma_f16(lf[1], paB[1], ONE2, ONE2);                                   \
    }                                                                         \
} while (0)

    CP_TILE(0, 0);
    CP_TILE(1, 64);

    // tile 0 (peeled): raw S, compute frozen offset
    {
        asm volatile("cp.async.wait_group 1;\n" ::);
        __syncthreads();
        CP_TILE(2, 128);

        float sc[2][8][4] = {};
        uint32_t pl[2][8], ph[2][8];
        S_PHASE(ks_base);

        #pragma unroll
        for (int mt = 0; mt < 2; mt++) {
            float mx0 = -1e30f, mx1 = -1e30f;
            #pragma unroll
            for (int nt = 0; nt < 8; nt++) {
                mx0 = fmaxf(mx0, fmaxf(sc[mt][nt][0], sc[mt][nt][1]));
                mx1 = fmaxf(mx1, fmaxf(sc[mt][nt][2], sc[mt][nt][3]));
            }
            mx0 = fmaxf(mx0, __shfl_xor_sync(0xffffffffu, mx0, 1));
            mx0 = fmaxf(mx0, __shfl_xor_sync(0xffffffffu, mx0, 2));
            mx1 = fmaxf(mx1, __shfl_xor_sync(0xffffffffu, mx1, 1));
            mx1 = fmaxf(mx1, __shfl_xor_sync(0xffffffffu, mx1, 2));
            nm[mt][0] = -mx0;
            nm[mt][1] = -mx1;
            #pragma unroll
            for (int nt = 0; nt < 8; nt++) {
                pl[mt][nt] = ex2h2(packh2(sc[mt][nt][0] + nm[mt][0],
                                          sc[mt][nt][1] + nm[mt][0]));
                ph[mt][nt] = ex2h2(packh2(sc[mt][nt][2] + nm[mt][1],
                                          sc[mt][nt][3] + nm[mt][1]));
            }
        }
        PV_PHASE(vs_base);
    }

    // tiles 1..NTILES-1: offset folded into accumulator init
    int st = 1;
    for (int t = 1; t < NTILES; t++) {
        if (t < NTILES - 1) {
            asm volatile("cp.async.wait_group 1;\n" ::);
        } else {
            asm volatile("cp.async.wait_group 0;\n" ::);
        }
        __syncthreads();

        const uint32_t ksb = ks_base + st * KS_STAGE;
        const uint32_t vsb = vs_base + st * VS_STAGE;

        float sc[2][8][4];
        #pragma unroll
        for (int mt = 0; mt < 2; mt++)
            #pragma unroll
            for (int nt = 0; nt < 8; nt++) {
                sc[mt][nt][0] = nm[mt][0];
                sc[mt][nt][1] = nm[mt][0];
                sc[mt][nt][2] = nm[mt][1];
                sc[mt][nt][3] = nm[mt][1];
            }

        S_PHASE(ksb);

        if (t + 2 < NTILES) {
            int st2 = st + 2; if (st2 >= 3) st2 -= 3;
            CP_TILE(st2, (t + 2) * 64);
        }

        uint32_t pl[2][8], ph[2][8];
        #pragma unroll
        for (int mt = 0; mt < 2; mt++) {
            #pragma unroll
            for (int nt = 0; nt < 8; nt++) {
                pl[mt][nt] = ex2h2(packh2(sc[mt][nt][0], sc[mt][nt][1]));
                ph[mt][nt] = ex2h2(packh2(sc[mt][nt][2], sc[mt][nt][3]));
            }
        }

        PV_PHASE(vsb);

        st++; if (st >= 3) st -= 3;
    }

    // finalize
    #pragma unroll
    for (int mt = 0; mt < 2; mt++) {
        float inv0 = 1.f / lf[mt][0];
        float inv1 = 1.f / lf[mt][2];
        int row0 = q0 + mt * 16 + r;
        __half* zp0 = z + (size_t)(b * N_ + row0) * HD + h * D_;
        __half* zp1 = zp0 + 8 * (size_t)HD;
        #pragma unroll
        for (int nt = 0; nt < 8; nt++) {
            int col = nt * 8 + 2 * qq;
            *(uint32_t*)(zp0 + col) = packh2(o[mt][nt][0] * inv0,
                                             o[mt][nt][1] * inv0);
            *(uint32_t*)(zp1 + col) = packh2(o[mt][nt][2] * inv1,
                                             o[mt][nt][3] * inv1);
        }
    }
}

// ---------------------------------------------------------------------------
// Output projection (fp16 mma): [16384,512] @ [512,64] + bias -> fp32
// ---------------------------------------------------------------------------
__global__ __launch_bounds__(256)
void out_gemm_kernel(const __half* __restrict__ z,
                     const __half* __restrict__ wt,
                     const float* __restrict__ bias,
                     float* __restrict__ out)
{
    extern __shared__ char smem_raw2[];
    __half*   swt = (__half*)smem_raw2;                       // [64][520]
    uint32_t* as  = (uint32_t*)(smem_raw2 + 64 * 520 * 2);    // 2 x 128 x 32 w

    const int tid  = threadIdx.x;
    const int warp = tid >> 5, lane = tid & 31;
    const int r = lane >> 2, qq = lane & 3;
    const int m0 = blockIdx.x * 128;

    const uint32_t wt_base = (uint32_t)__cvta_generic_to_shared(swt);
    const uint32_t as_base = (uint32_t)__cvta_generic_to_shared(as);

#define CPA(stage, kc) do {                                                   \
    _Pragma("unroll")                                                         \
    for (int it = 0; it < 4; it++) {                                          \
        int idx = tid + it * 256;                                             \
        int rr = idx >> 3, c4 = idx & 7;                                      \
        cp16(as_base + (uint32_t)((stage) * 16384 + rr * 128 +                \
                                  ((c4 ^ (rr & 7)) * 16)),                    \
             z + (size_t)(m0 + rr) * HD + (kc) * 64 + c4 * 8);                \
    }                                                                         \
    asm volatile("cp.async.commit_group;\n" ::);                              \
} while (0)

    #pragma unroll
    for (int it = 0; it < 16; it++) {
        int idx = tid + it * 256;
        int n = idx >> 6, c = idx & 63;
        cp16(wt_base + (uint32_t)(n * 1040 + c * 16), wt + n * 520 + c * 8);
    }
    CPA(0, 0);

    float acc[8][4] = {};

    for (int kc = 0; kc < 8; kc++) {
        const int s = kc & 1;
        if (kc < 7) {
            CPA(s ^ 1, kc + 1);
            asm volatile("cp.async.wait_group 1;\n" ::);
        } else {
            asm volatile("cp.async.wait_group 0;\n" ::);
        }
        __syncthreads();

        const uint32_t* asw = as + s * 4096;
        const int rowa0 = warp * 16 + r;
        const int rowa1 = rowa0 + 8;

        #pragma unroll
        for (int kt = 0; kt < 4; kt++) {
            uint32_t a[4];
            a[0] = asw[rowa0 * 32 + (((2*kt)   ^ r) << 2) + qq];
            a[1] = asw[rowa1 * 32 + (((2*kt)   ^ r) << 2) + qq];
            a[2] = asw[rowa0 * 32 + (((2*kt+1) ^ r) << 2) + qq];
            a[3] = asw[rowa1 * 32 + (((2*kt+1) ^ r) << 2) + qq];
            #pragma unroll
            for (int nt = 0; nt < 8; nt++) {
                int n = nt * 8 + r;
                const __half* wp = swt + n * 520 + kc * 64 + kt * 16 + 2 * qq;
                uint32_t b0 = *(const uint32_t*)wp;
                uint32_t b1 = *(const uint32_t*)(wp + 8);
                mma_f16(acc[nt], a, b0, b1);
            }
        }
        __syncthreads();
    }

    #pragma unroll
    for (int nt = 0; nt < 8; nt++) {
        int row0 = m0 + warp * 16 + r;
        int col  = nt * 8 + 2 * qq;
        float bx = bias[col], by = bias[col + 1];
        float2 v0 = {acc[nt][0] + bx, acc[nt][1] + by};
        float2 v1 = {acc[nt][2] + bx, acc[nt][3] + by};
        *(float2*)(out + (size_t)row0 * 64 + col)       = v0;
        *(float2*)(out + (size_t)(row0 + 8) * 64 + col) = v1;
    }
}

// ---------------------------------------------------------------------------
extern "C" void kernel_launch(void* const* d_in, const int* in_sizes, int n_in,
                              void* d_out, int out_size)
{
    const float* x    = (const float*)d_in[0];
    const float* Wqkv = (const float*)d_in[1];
    const float* Wout = (const float*)d_in[2];
    const float* bout = (const float*)d_in[3];
    float* out = (float*)d_out;

    __half *qp, *kp, *vtp, *zp, *wtp, *wqp;
    cudaGetSymbolAddress((void**)&qp,  g_q);
    cudaGetSymbolAddress((void**)&kp,  g_k);
    cudaGetSymbolAddress((void**)&vtp, g_vt);
    cudaGetSymbolAddress((void**)&zp,  g_z);
    cudaGetSymbolAddress((void**)&wtp, g_wt);
    cudaGetSymbolAddress((void**)&wqp, g_wq);

    prep_kernel<<<512, 256>>>(Wqkv, Wout, wqp, wtp);
    {
        cudaFuncSetAttribute(qkv_gemm_kernel,
                             cudaFuncAttributeMaxDynamicSharedMemorySize,
                             QKV_SMEM);
        qkv_gemm_kernel<<<M_ / 64, 256, QKV_SMEM>>>(x, wqp, qp, kp, vtp);
    }
    {
        cudaFuncSetAttribute(attn_kernel,
                             cudaFuncAttributeMaxDynamicSharedMemorySize,
                             ATTN_SMEM);
        dim3 grid(N_ / 128, B_ * H_);
        attn_kernel<<<grid, 128, ATTN_SMEM>>>(qp, kp, vtp, zp);
    }
    {
        const int smem = 64 * 520 * 2 + 2 * 16384;   // 99328 B
        cudaFuncSetAttribute(out_gemm_kernel,
                             cudaFuncAttributeMaxDynamicSharedMemorySize, smem);
        out_gemm_kernel<<<M_ / 128, 256, smem>>>(zp, wtp, bout, out);
    }
}

// round 15
// speedup vs baseline: 2.0965x; 1.0046x over previous
#include <cuda_runtime.h>
#include <cuda_fp16.h>
#include <stdint.h>

#define B_   8
#define N_   2048
#define D_   64
#define H_   8
#define M_   (B_*N_)        // 16384
#define QKVN 1536
#define HD   512
#define QSCALE (0.125f * 1.44269504088896f)   // 1/sqrt(d) * log2(e)

// Scratch (__device__ globals; allocation-free rule)
__device__ __half g_q [(size_t)M_ * HD];
__device__ __half g_k [(size_t)M_ * HD];
__device__ __half g_vt[(size_t)B_*H_*D_*N_];      // [bh][d][tok]
__device__ __half g_z [(size_t)M_ * HD];
__device__ __half g_wt[64 * 520];                 // Wout^T fp16 [n][k]
__device__ __half g_wq[12 * 128 * 64];            // Wqkv^T fp16 [tile][n][k]

// ---------------------------------------------------------------------------
// helpers
// ---------------------------------------------------------------------------
__device__ __forceinline__ uint32_t ex2h2(uint32_t x) {
    uint32_t y; asm("ex2.approx.f16x2 %0, %1;" : "=r"(y) : "r"(x)); return y;
}
__device__ __forceinline__ uint32_t packh2(float lo, float hi) {
    uint32_t u;
    asm("cvt.rn.f16x2.f32 %0, %1, %2;" : "=r"(u) : "f"(hi), "f"(lo));
    return u;
}
__device__ __forceinline__ void mma_f16(float d[4], const uint32_t a[4],
                                        uint32_t b0, uint32_t b1) {
    asm volatile(
        "mma.sync.aligned.m16n8k16.row.col.f32.f16.f16.f32 "
        "{%0,%1,%2,%3}, {%4,%5,%6,%7}, {%8,%9}, {%0,%1,%2,%3};\n"
        : "+f"(d[0]), "+f"(d[1]), "+f"(d[2]), "+f"(d[3])
        : "r"(a[0]), "r"(a[1]), "r"(a[2]), "r"(a[3]), "r"(b0), "r"(b1));
}
__device__ __forceinline__ void cp16(uint32_t dst_smem, const void* src) {
    asm volatile("cp.async.cg.shared.global [%0], [%1], 16;\n"
                 :: "r"(dst_smem), "l"(src));
}
__device__ __forceinline__ void ldsm_x4(uint32_t r[4], uint32_t addr) {
    asm volatile(
        "ldmatrix.sync.aligned.m8n8.x4.shared.b16 {%0,%1,%2,%3}, [%4];\n"
        : "=r"(r[0]), "=r"(r[1]), "=r"(r[2]), "=r"(r[3]) : "r"(addr));
}

// ---------------------------------------------------------------------------
// prep: Wqkv [64][1536] -> g_wq [12][128][64] fp16 (transposed, tile-major)
//       Wout [512][64]  -> g_wt [64][520]     fp16 (transposed)
// ---------------------------------------------------------------------------
__global__ __launch_bounds__(256)
void prep_kernel(const float* __restrict__ Wqkv, const float* __restrict__ Wout,
                 __half* __restrict__ wq, __half* __restrict__ wt)
{
    int idx = blockIdx.x * 256 + threadIdx.x;          // 0 .. 131071
    if (idx < 98304) {
        int k = idx / QKVN;            // 0..63
        int n = idx - k * QKVN;        // 0..1535 (coalesced read)
        wq[(size_t)(n >> 7) * 8192 + (n & 127) * 64 + k] =
            __float2half_rn(Wqkv[idx]);
    } else {
        int j = idx - 98304;           // 0..32767
        int k = j >> 6, n = j & 63;
        wt[n * 520 + k] = __float2half_rn(Wout[j]);
    }
}

// ---------------------------------------------------------------------------
// QKV GEMM (fp16 mma, persistent over n): [16384,64] @ [64,1536]
// 256 blocks (one 64-row m-tile each), 256 threads / 8 warps.
// x A-frags loaded ONCE; W fp16 streamed via 3-stage cp.async ring.
// ---------------------------------------------------------------------------
#define WST 18432                       // stage: 128 rows x 144 B
#define QKV_SMEM (3 * WST + 18432)      // + sv transpose buffer = 73728 B

__global__ __launch_bounds__(256)
void qkv_gemm_kernel(const float* __restrict__ x,
                     const __half* __restrict__ wq,
                     __half* __restrict__ q,
                     __half* __restrict__ kk,
                     __half* __restrict__ vt)
{
    extern __shared__ __align__(16) char smem_raw[];
    __half (*sv)[72] = (__half(*)[72])(smem_raw + 3 * WST);

    const int tid  = threadIdx.x;
    const int warp = tid >> 5, lane = tid & 31;
    const int r = lane >> 2, qq = lane & 3;
    const int wm = warp >> 1, wn = warp & 1;
    const int m0 = blockIdx.x * 64;

    const uint32_t sb = (uint32_t)__cvta_generic_to_shared(smem_raw);

#define CPW(stg, tn_) do {                                                    \
    _Pragma("unroll")                                                         \
    for (int it = 0; it < 4; it++) {                                          \
        int idx = tid + it * 256;                                             \
        int n = idx >> 3, c = idx & 7;                                        \
        cp16(sb + (uint32_t)((stg) * WST + n * 144 + c * 16),                 \
             wq + (size_t)(tn_) * 8192 + n * 64 + c * 8);                     \
    }                                                                         \
    asm volatile("cp.async.commit_group;\n" ::);                              \
} while (0)

    CPW(0, 0);
    CPW(1, 1);

    // x A-frags, loaded once (float2 -> packed fp16)
    uint32_t qa[4][4];
    {
        const float* p0 = x + (size_t)(m0 + wm * 16 + r) * 64;
        const float* p1 = p0 + 8 * 64;
        #pragma unroll
        for (int kt = 0; kt < 4; kt++) {
            int c = kt * 16 + 2 * qq;
            float2 a0 = *(const float2*)(p0 + c);
            float2 a1 = *(const float2*)(p1 + c);
            float2 a2 = *(const float2*)(p0 + c + 8);
            float2 a3 = *(const float2*)(p1 + c + 8);
            qa[kt][0] = packh2(a0.x, a0.y);
            qa[kt][1] = packh2(a1.x, a1.y);
            qa[kt][2] = packh2(a2.x, a2.y);
            qa[kt][3] = packh2(a3.x, a3.y);
        }
    }

    int st = 0;
    #pragma unroll 1
    for (int tn = 0; tn < 12; tn++) {
        if (tn < 11) { asm volatile("cp.async.wait_group 1;\n" ::); }
        else         { asm volatile("cp.async.wait_group 0;\n" ::); }
        __syncthreads();

        if (tn + 2 < 12) {
            int st2 = st + 2; if (st2 >= 3) st2 -= 3;
            CPW(st2, tn + 2);
        }

        const uint32_t wst = sb + st * WST;

        float acc[8][4] = {};
        #pragma unroll
        for (int kt = 0; kt < 4; kt++) {
            #pragma unroll
            for (int nt = 0; nt < 8; nt++) {
                int n = wn * 64 + nt * 8 + r;
                uint32_t addr = wst + n * 144 + (kt * 16 + 2 * qq) * 2;
                uint32_t b0, b1;
                asm volatile("ld.shared.b32 %0, [%1];" : "=r"(b0) : "r"(addr));
                asm volatile("ld.shared.b32 %0, [%1];" : "=r"(b1) : "r"(addr + 16));
                mma_f16(acc[nt], qa[kt], b0, b1);
            }
        }

        const int n0 = tn * 128;
        if (n0 < 1024) {
            const float s = (n0 < 512) ? QSCALE : 1.0f;
            __half* dst = (n0 < 512) ? q : kk;
            const int cbase = (n0 < 512) ? n0 : (n0 - 512);
            #pragma unroll
            for (int nt = 0; nt < 8; nt++) {
                int row0 = m0 + wm * 16 + r;
                int col  = cbase + wn * 64 + nt * 8 + 2 * qq;
                *(uint32_t*)(dst + (size_t)row0 * HD + col) =
                    packh2(acc[nt][0] * s, acc[nt][1] * s);
                *(uint32_t*)(dst + (size_t)(row0 + 8) * HD + col) =
                    packh2(acc[nt][2] * s, acc[nt][3] * s);
            }
        } else {
            // V: transpose via smem, then coalesced STG.128
            #pragma unroll
            for (int nt = 0; nt < 8; nt++) {
                int row_l = wm * 16 + r;
                int col_l = wn * 64 + nt * 8 + 2 * qq;
                sv[col_l    ][row_l]     = __float2half_rn(acc[nt][0]);
                sv[col_l + 1][row_l]     = __float2half_rn(acc[nt][1]);
                sv[col_l    ][row_l + 8] = __float2half_rn(acc[nt][2]);
                sv[col_l + 1][row_l + 8] = __float2half_rn(acc[nt][3]);
            }
            __syncthreads();
            const int h0   = (n0 - 1024) >> 6;
            const int b    = m0 >> 11;
            const int tok0 = m0 & 2047;
            #pragma unroll
            for (int it = 0; it < 4; it++) {
                int idx = tid + it * 256;
                int col = idx >> 3, c8 = idx & 7;
                uint4 v = *(uint4*)&sv[col][c8 * 8];
                int h = h0 + (col >> 6), d = col & 63;
                *(uint4*)(vt + ((size_t)((b * 8 + h) * 64 + d)) * N_ +
                          tok0 + c8 * 8) = v;
            }
        }

        st++; if (st >= 3) st -= 3;
    }
}

// ---------------------------------------------------------------------------
// Flash attention (best known): 128 threads / 4 warps, warp = 32 q rows, LDSM,
// 3-stage cp.async ring, frozen offset folded into S accumulator init.
// ---------------------------------------------------------------------------
#define VSTRIDE 88
#define KS_STAGE 8192
#define VS_STAGE (64 * VSTRIDE * 2)          // 11264
#define ATTN_SMEM (3 * (KS_STAGE + VS_STAGE))
#define NTILES (N_ / 64)

__global__ __launch_bounds__(128)
void attn_kernel(const __half* __restrict__ q,
                 const __half* __restrict__ kglb,
                 const __half* __restrict__ vt,
                 __half* __restrict__ z)
{
    extern __shared__ __align__(16) char smem_raw[];

    const int tid  = threadIdx.x;
    const int warp = tid >> 5, lane = tid & 31;
    const int r = lane >> 2, qq = lane & 3;
    const int lrow = lane & 7;
    const int ltile = lane >> 3;
    const int bh = blockIdx.y;
    const int b = bh >> 3, h = bh & 7;
    const int q0 = blockIdx.x * 128 + warp * 32;
    const uint32_t ONE2 = 0x3C003C00u;

    uint32_t qa[2][4][4];
    #pragma unroll
    for (int mt = 0; mt < 2; mt++) {
        const __half* p0 = q + (size_t)(b * N_ + q0 + mt * 16 + r) * HD + h * D_;
        const __half* p1 = p0 + 8 * (size_t)HD;
        #pragma unroll
        for (int kt = 0; kt < 4; kt++) {
            int c = kt * 16 + 2 * qq;
            qa[mt][kt][0] = *(const uint32_t*)(p0 + c);
            qa[mt][kt][1] = *(const uint32_t*)(p1 + c);
            qa[mt][kt][2] = *(const uint32_t*)(p0 + c + 8);
            qa[mt][kt][3] = *(const uint32_t*)(p1 + c + 8);
        }
    }

    float o[2][8][4] = {};
    float lf[2][4] = {};
    float nm[2][2];                       // NEGATIVE frozen offsets

    const __half* kb = kglb + (size_t)(b * N_) * HD + h * D_;
    const __half* vb = vt + (size_t)bh * D_ * N_;

    const uint32_t ks_base = (uint32_t)__cvta_generic_to_shared(smem_raw);
    const uint32_t vs_base = ks_base + 3 * KS_STAGE;

    const uint32_t kx0 = (uint32_t)(((0 * 4 + ltile) ^ lrow) * 16) + lrow * 128;
    const uint32_t kx1 = (uint32_t)(((1 * 4 + ltile) ^ lrow) * 16) + lrow * 128;
    const uint32_t vx  = (uint32_t)((lrow * VSTRIDE + ltile * 8) * 2);

#define CP_TILE(stage, j0) do {                                               \
    _Pragma("unroll")                                                         \
    for (int it = 0; it < 4; it++) {                                          \
        int idx = tid + it * 128;                                             \
        int rr = idx >> 3, c4 = idx & 7;                                      \
        cp16(ks_base + (uint32_t)((stage) * KS_STAGE + rr * 128 +             \
                                  ((c4 ^ (rr & 7)) * 16)),                    \
             kb + (size_t)((j0) + rr) * HD + c4 * 8);                         \
    }                                                                         \
    _Pragma("unroll")                                                         \
    for (int it = 0; it < 4; it++) {                                          \
        int idx = tid + it * 128;                                             \
        int dd = idx >> 3, c8 = idx & 7;                                      \
        cp16(vs_base + (uint32_t)((stage) * VS_STAGE +                        \
                                  (dd * VSTRIDE + c8 * 8) * 2),               \
             vb + (size_t)dd * N_ + (j0) + c8 * 8);                           \
    }                                                                         \
    asm volatile("cp.async.commit_group;\n" ::);                              \
} while (0)

#define S_PHASE(ksb_) do {                                                    \
    _Pragma("unroll")                                                         \
    for (int ktp = 0; ktp < 2; ktp++) {                                       \
        const uint32_t kx = ktp ? kx1 : kx0;                                  \
        _Pragma("unroll")                                                     \
        for (int nt = 0; nt < 8; nt++) {                                      \
            uint32_t kbf[4];                                                  \
            ldsm_x4(kbf, (ksb_) + nt * 1024 + kx);                            \
            mma_f16(sc[0][nt], qa[0][2*ktp],   kbf[0], kbf[1]);               \
            mma_f16(sc[1][nt], qa[1][2*ktp],   kbf[0], kbf[1]);               \
            mma_f16(sc[0][nt], qa[0][2*ktp+1], kbf[2], kbf[3]);               \
            mma_f16(sc[1][nt], qa[1][2*ktp+1], kbf[2], kbf[3]);               \
        }                                                                     \
    }                                                                         \
} while (0)

#define PV_PHASE(vsb_) do {                                                   \
    _Pragma("unroll")                                                         \
    for (int ktp = 0; ktp < 2; ktp++) {                                       \
        uint32_t paA[2][4], paB[2][4];                                        \
        _Pragma("unroll")                                                     \
        for (int mt = 0; mt < 2; mt++) {                                      \
            paA[mt][0] = pl[mt][4*ktp + 0];                                   \
            paA[mt][1] = ph[mt][4*ktp + 0];                                   \
            paA[mt][2] = pl[mt][4*ktp + 1];                                   \
            paA[mt][3] = ph[mt][4*ktp + 1];                                   \
            paB[mt][0] = pl[mt][4*ktp + 2];                                   \
            paB[mt][1] = ph[mt][4*ktp + 2];                                   \
            paB[mt][2] = pl[mt][4*ktp + 3];                                   \
            paB[mt][3] = ph[mt][4*ktp + 3];                                   \
        }                                                                     \
        _Pragma("unroll")                                                     \
        for (int nt = 0; nt < 8; nt++) {                                      \
            uint32_t vbf[4];                                                  \
            ldsm_x4(vbf, (vsb_) + nt * (8 * VSTRIDE * 2) + ktp * 64 + vx);    \
            mma_f16(o[0][nt], paA[0], vbf[0], vbf[1]);                        \
            mma_f16(o[1][nt], paA[1], vbf[0], vbf[1]);                        \
            mma_f16(o[0][nt], paB[0], vbf[2], vbf[3]);                        \
            mma_f16(o[1][nt], paB[1], vbf[2], vbf[3]);                        \
        }                                                                     \
        mma_f16(lf[0], paA[0], ONE2, ONE2);                                   \
        mma_f16(lf[1], paA[1], ONE2, ONE2);                                   \
        mma_f16(lf[0], paB[0], ONE2, ONE2);                                   \
        mma_f16(lf[1], paB[1], ONE2, ONE2);                                   \
    }                                                                         \
} while (0)

    CP_TILE(0, 0);
    CP_TILE(1, 64);

    // tile 0 (peeled): raw S, compute frozen offset
    {
        asm volatile("cp.async.wait_group 1;\n" ::);
        __syncthreads();
        CP_TILE(2, 128);

        float sc[2][8][4] = {};
        uint32_t pl[2][8], ph[2][8];
        S_PHASE(ks_base);

        #pragma unroll
        for (int mt = 0; mt < 2; mt++) {
            float mx0 = -1e30f, mx1 = -1e30f;
            #pragma unroll
            for (int nt = 0; nt < 8; nt++) {
                mx0 = fmaxf(mx0, fmaxf(sc[mt][nt][0], sc[mt][nt][1]));
                mx1 = fmaxf(mx1, fmaxf(sc[mt][nt][2], sc[mt][nt][3]));
            }
            mx0 = fmaxf(mx0, __shfl_xor_sync(0xffffffffu, mx0, 1));
            mx0 = fmaxf(mx0, __shfl_xor_sync(0xffffffffu, mx0, 2));
            mx1 = fmaxf(mx1, __shfl_xor_sync(0xffffffffu, mx1, 1));
            mx1 = fmaxf(mx1, __shfl_xor_sync(0xffffffffu, mx1, 2));
            nm[mt][0] = -mx0;
            nm[mt][1] = -mx1;
            #pragma unroll
            for (int nt = 0; nt < 8; nt++) {
                pl[mt][nt] = ex2h2(packh2(sc[mt][nt][0] + nm[mt][0],
                                          sc[mt][nt][1] + nm[mt][0]));
                ph[mt][nt] = ex2h2(packh2(sc[mt][nt][2] + nm[mt][1],
                                          sc[mt][nt][3] + nm[mt][1]));
            }
        }
        PV_PHASE(vs_base);
    }

    // tiles 1..NTILES-1: offset folded into accumulator init
    int st = 1;
    for (int t = 1; t < NTILES; t++) {
        if (t < NTILES - 1) {
            asm volatile("cp.async.wait_group 1;\n" ::);
        } else {
            asm volatile("cp.async.wait_group 0;\n" ::);
        }
        __syncthreads();

        const uint32_t ksb = ks_base + st * KS_STAGE;
        const uint32_t vsb = vs_base + st * VS_STAGE;

        float sc[2][8][4];
        #pragma unroll
        for (int mt = 0; mt < 2; mt++)
            #pragma unroll
            for (int nt = 0; nt < 8; nt++) {
                sc[mt][nt][0] = nm[mt][0];
                sc[mt][nt][1] = nm[mt][0];
                sc[mt][nt][2] = nm[mt][1];
                sc[mt][nt][3] = nm[mt][1];
            }

        S_PHASE(ksb);

        if (t + 2 < NTILES) {
            int st2 = st + 2; if (st2 >= 3) st2 -= 3;
            CP_TILE(st2, (t + 2) * 64);
        }

        uint32_t pl[2][8], ph[2][8];
        #pragma unroll
        for (int mt = 0; mt < 2; mt++) {
            #pragma unroll
            for (int nt = 0; nt < 8; nt++) {
                pl[mt][nt] = ex2h2(packh2(sc[mt][nt][0], sc[mt][nt][1]));
                ph[mt][nt] = ex2h2(packh2(sc[mt][nt][2], sc[mt][nt][3]));
            }
        }

        PV_PHASE(vsb);

        st++; if (st >= 3) st -= 3;
    }

    // finalize
    #pragma unroll
    for (int mt = 0; mt < 2; mt++) {
        float inv0 = 1.f / lf[mt][0];
        float inv1 = 1.f / lf[mt][2];
        int row0 = q0 + mt * 16 + r;
        __half* zp0 = z + (size_t)(b * N_ + row0) * HD + h * D_;
        __half* zp1 = zp0 + 8 * (size_t)HD;
        #pragma unroll
        for (int nt = 0; nt < 8; nt++) {
            int col = nt * 8 + 2 * qq;
            *(uint32_t*)(zp0 + col) = packh2(o[mt][nt][0] * inv0,
                                             o[mt][nt][1] * inv0);
            *(uint32_t*)(zp1 + col) = packh2(o[mt][nt][2] * inv1,
                                             o[mt][nt][3] * inv1);
        }
    }
}

// ---------------------------------------------------------------------------
// Output projection (fp16 mma): [16384,512] @ [512,64] + bias -> fp32
// 256 blocks x 64 rows; 8 warps: warp = 16 rows x 32-col n-half.
// ---------------------------------------------------------------------------
#define OUT_SMEM (64 * 520 * 2 + 2 * 8192)   // W tile + 2 x (64 rows x 128B)

__global__ __launch_bounds__(256)
void out_gemm_kernel(const __half* __restrict__ z,
                     const __half* __restrict__ wt,
                     const float* __restrict__ bias,
                     float* __restrict__ out)
{
    extern __shared__ char smem_raw2[];
    __half*   swt = (__half*)smem_raw2;                       // [64][520]
    uint32_t* as  = (uint32_t*)(smem_raw2 + 64 * 520 * 2);    // 2 x 64 x 32 w

    const int tid  = threadIdx.x;
    const int warp = tid >> 5, lane = tid & 31;
    const int r = lane >> 2, qq = lane & 3;
    const int wm = warp & 3;            // 16-row slice
    const int wh = warp >> 2;           // 32-col n-half
    const int m0 = blockIdx.x * 64;

    const uint32_t wt_base = (uint32_t)__cvta_generic_to_shared(swt);
    const uint32_t as_base = (uint32_t)__cvta_generic_to_shared(as);

#define CPA(stage, kc) do {                                                   \
    _Pragma("unroll")                                                         \
    for (int it = 0; it < 2; it++) {                                          \
        int idx = tid + it * 256;                                             \
        int rr = idx >> 3, c4 = idx & 7;                                      \
        cp16(as_base + (uint32_t)((stage) * 8192 + rr * 128 +                 \
                                  ((c4 ^ (rr & 7)) * 16)),                    \
             z + (size_t)(m0 + rr) * HD + (kc) * 64 + c4 * 8);                \
    }                                                                         \
    asm volatile("cp.async.commit_group;\n" ::);                              \
} while (0)

    #pragma unroll
    for (int it = 0; it < 16; it++) {
        int idx = tid + it * 256;
        int n = idx >> 6, c = idx & 63;
        cp16(wt_base + (uint32_t)(n * 1040 + c * 16), wt + n * 520 + c * 8);
    }
    CPA(0, 0);

    float acc[4][4] = {};

    for (int kc = 0; kc < 8; kc++) {
        const int s = kc & 1;
        if (kc < 7) {
            CPA(s ^ 1, kc + 1);
            asm volatile("cp.async.wait_group 1;\n" ::);
        } else {
            asm volatile("cp.async.wait_group 0;\n" ::);
        }
        __syncthreads();

        const uint32_t* asw = as + s * 2048;
        const int rowa0 = wm * 16 + r;
        const int rowa1 = rowa0 + 8;

        #pragma unroll
        for (int kt = 0; kt < 4; kt++) {
            uint32_t a[4];
            a[0] = asw[rowa0 * 32 + (((2*kt)   ^ r) << 2) + qq];
            a[1] = asw[rowa1 * 32 + (((2*kt)   ^ r) << 2) + qq];
            a[2] = asw[rowa0 * 32 + (((2*kt+1) ^ r) << 2) + qq];
            a[3] = asw[rowa1 * 32 + (((2*kt+1) ^ r) << 2) + qq];
            #pragma unroll
            for (int nt = 0; nt < 4; nt++) {
                int n = wh * 32 + nt * 8 + r;
                const __half* wp = swt + n * 520 + kc * 64 + kt * 16 + 2 * qq;
                uint32_t b0 = *(const uint32_t*)wp;
                uint32_t b1 = *(const uint32_t*)(wp + 8);
                mma_f16(acc[nt], a, b0, b1);
            }
        }
        __syncthreads();
    }

    #pragma unroll
    for (int nt = 0; nt < 4; nt++) {
        int row0 = m0 + wm * 16 + r;
        int col  = wh * 32 + nt * 8 + 2 * qq;
        float bx = bias[col], by = bias[col + 1];
        float2 v0 = {acc[nt][0] + bx, acc[nt][1] + by};
        float2 v1 = {acc[nt][2] + bx, acc[nt][3] + by};
        *(float2*)(out + (size_t)row0 * 64 + col)       = v0;
        *(float2*)(out + (size_t)(row0 + 8) * 64 + col) = v1;
    }
}

// ---------------------------------------------------------------------------
extern "C" void kernel_launch(void* const* d_in, const int* in_sizes, int n_in,
                              void* d_out, int out_size)
{
    const float* x    = (const float*)d_in[0];
    const float* Wqkv = (const float*)d_in[1];
    const float* Wout = (const float*)d_in[2];
    const float* bout = (const float*)d_in[3];
    float* out = (float*)d_out;

    __half *qp, *kp, *vtp, *zp, *wtp, *wqp;
    cudaGetSymbolAddress((void**)&qp,  g_q);
    cudaGetSymbolAddress((void**)&kp,  g_k);
    cudaGetSymbolAddress((void**)&vtp, g_vt);
    cudaGetSymbolAddress((void**)&zp,  g_z);
    cudaGetSymbolAddress((void**)&wtp, g_wt);
    cudaGetSymbolAddress((void**)&wqp, g_wq);

    prep_kernel<<<512, 256>>>(Wqkv, Wout, wqp, wtp);
    {
        cudaFuncSetAttribute(qkv_gemm_kernel,
                             cudaFuncAttributeMaxDynamicSharedMemorySize,
                             QKV_SMEM);
        qkv_gemm_kernel<<<M_ / 64, 256, QKV_SMEM>>>(x, wqp, qp, kp, vtp);
    }
    {
        cudaFuncSetAttribute(attn_kernel,
                             cudaFuncAttributeMaxDynamicSharedMemorySize,
                             ATTN_SMEM);
        dim3 grid(N_ / 128, B_ * H_);
        attn_kernel<<<grid, 128, ATTN_SMEM>>>(qp, kp, vtp, zp);
    }
    {
        cudaFuncSetAttribute(out_gemm_kernel,
                             cudaFuncAttributeMaxDynamicSharedMemorySize,
                             OUT_SMEM);
        out_gemm_kernel<<<M_ / 64, 256, OUT_SMEM>>>(zp, wtp, bout, out);
    }
}